// round 15
// baseline (speedup 1.0000x reference)
#include <cuda_runtime.h>
#include <cuda_bf16.h>
#include <cstdint>

#define B_     4
#define N_     2048
#define DIM_   2048
#define H_     16
#define DH_    128
#define TOK_   (B_ * N_)
#define QKVC_  (3 * DIM_)
#define BH_    (B_ * H_)

__device__ float          g_ss[B_ * 2 * DIM_];
__device__ __nv_bfloat16  g_xnh[(long long)TOK_ * DIM_];
__device__ __nv_bfloat16  g_xnl[(long long)TOK_ * DIM_];
__device__ __nv_bfloat16  g_wqTh[(long long)QKVC_ * DIM_];
__device__ __nv_bfloat16  g_wqTl[(long long)QKVC_ * DIM_];
__device__ __nv_bfloat16  g_woTh[(long long)DIM_ * DIM_];
__device__ __nv_bfloat16  g_woTl[(long long)DIM_ * DIM_];
__device__ __nv_bfloat16  g_qkh[(long long)TOK_ * 2 * DIM_];
__device__ __nv_bfloat16  g_qkl[(long long)TOK_ * 2 * DIM_];
__device__ __nv_bfloat16  g_vTh[(long long)BH_ * DH_ * N_];
__device__ __nv_bfloat16  g_vTl[(long long)BH_ * DH_ * N_];
__device__ __nv_bfloat16  g_oh[(long long)TOK_ * DIM_];
__device__ __nv_bfloat16  g_ol[(long long)TOK_ * DIM_];

__device__ __forceinline__ uint32_t smem_u32(const void* p) {
    uint32_t a;
    asm("{ .reg .u64 t; cvta.to.shared.u64 t, %1; cvt.u32.u64 %0, t; }"
        : "=r"(a) : "l"(p));
    return a;
}
__device__ __forceinline__ void cp16(uint32_t dst, const void* src) {
    asm volatile("cp.async.cg.shared.global [%0], [%1], 16;"
                 :: "r"(dst), "l"(__cvta_generic_to_global(src)));
}
__device__ __forceinline__ void cp_commit() {
    asm volatile("cp.async.commit_group;" ::: "memory");
}
template <int NN>
__device__ __forceinline__ void cp_wait() {
    asm volatile("cp.async.wait_group %0;" :: "n"(NN) : "memory");
}
__device__ __forceinline__ void ldsm4(uint32_t& r0, uint32_t& r1,
                                      uint32_t& r2, uint32_t& r3, uint32_t a) {
    asm volatile("ldmatrix.sync.aligned.m8n8.x4.shared.b16 {%0,%1,%2,%3}, [%4];"
                 : "=r"(r0), "=r"(r1), "=r"(r2), "=r"(r3) : "r"(a));
}
__device__ __forceinline__ void mma16816(float* d, const uint32_t* a,
                                         const uint32_t* b) {
    asm volatile(
        "mma.sync.aligned.m16n8k16.row.col.f32.bf16.bf16.f32 "
        "{%0,%1,%2,%3}, {%4,%5,%6,%7}, {%8,%9}, {%0,%1,%2,%3};"
        : "+f"(d[0]), "+f"(d[1]), "+f"(d[2]), "+f"(d[3])
        : "r"(a[0]), "r"(a[1]), "r"(a[2]), "r"(a[3]), "r"(b[0]), "r"(b[1]));
}
__device__ __forceinline__ void st32(uint32_t a, uint32_t v) {
    asm volatile("st.shared.b32 [%0], %1;" :: "r"(a), "r"(v) : "memory");
}
__device__ __forceinline__ void split_store4(float4 v,
                                             __nv_bfloat16* __restrict__ hi,
                                             __nv_bfloat16* __restrict__ lo) {
    __nv_bfloat16 h[4], l[4];
    float f[4] = {v.x, v.y, v.z, v.w};
    #pragma unroll
    for (int i = 0; i < 4; i++) {
        h[i] = __float2bfloat16(f[i]);
        l[i] = __float2bfloat16(f[i] - __bfloat162float(h[i]));
    }
    *(uint2*)hi = *(const uint2*)h;
    *(uint2*)lo = *(const uint2*)l;
}
__device__ __forceinline__ uint32_t pack_hi2(float a, float b) {
    __nv_bfloat16 h[2] = {__float2bfloat16(a), __float2bfloat16(b)};
    return *(const uint32_t*)h;
}
__device__ __forceinline__ uint32_t pack_lo2(float a, float b) {
    __nv_bfloat16 ha = __float2bfloat16(a), hb = __float2bfloat16(b);
    __nv_bfloat16 l[2] = {__float2bfloat16(a - __bfloat162float(ha)),
                          __float2bfloat16(b - __bfloat162float(hb))};
    return *(const uint32_t*)l;
}
__device__ __forceinline__ float2 unp2(uint32_t u) {
    __nv_bfloat16* p = (__nv_bfloat16*)&u;
    return make_float2(__bfloat162float(p[0]), __bfloat162float(p[1]));
}
__device__ __forceinline__ float blk_sum256(float v) {
    __shared__ float red[8];
    __shared__ float tot;
    #pragma unroll
    for (int o = 16; o > 0; o >>= 1) v += __shfl_xor_sync(0xffffffffu, v, o);
    if ((threadIdx.x & 31) == 0) red[threadIdx.x >> 5] = v;
    __syncthreads();
    if (threadIdx.x == 0) {
        float s = 0.f;
        #pragma unroll
        for (int i = 0; i < 8; i++) s += red[i];
        tot = s;
    }
    __syncthreads();
    return tot;
}

__global__ void k_scale_shift(const float* __restrict__ emb,
                              const float* __restrict__ W,
                              const float* __restrict__ bias,
                              float* __restrict__ ss) {
    int c = blockIdx.x * 256 + threadIdx.x;
    int b = blockIdx.y;
    const float* e = emb + b * DIM_;
    float acc = bias[c];
    const float* wp = W + c;
    #pragma unroll 8
    for (int k = 0; k < DIM_; k++)
        acc = fmaf(e[k], wp[(long long)k * (2 * DIM_)], acc);
    ss[b * (2 * DIM_) + c] = acc;
}

__global__ void k_xnorm(const float* __restrict__ x,
                        const float* __restrict__ g,
                        const float* __restrict__ ss,
                        __nv_bfloat16* __restrict__ xh,
                        __nv_bfloat16* __restrict__ xl) {
    long long row = blockIdx.x;
    int b = (int)(row >> 11);
    const float4* xr = (const float4*)(x + row * DIM_);
    float4 v0 = xr[threadIdx.x];
    float4 v1 = xr[threadIdx.x + 256];
    float s = v0.x * v0.x + v0.y * v0.y + v0.z * v0.z + v0.w * v0.w
            + v1.x * v1.x + v1.y * v1.y + v1.z * v1.z + v1.w * v1.w;
    s = blk_sum256(s);
    float r = rsqrtf(s * (1.f / DIM_) + 1e-6f);
    const float* sc = ss + b * (2 * DIM_);
    const float* sh = sc + DIM_;
    int c0 = threadIdx.x * 4, c1 = (threadIdx.x + 256) * 4;
    float4 o0, o1;
    o0.x = fmaf(v0.x * r * g[c0 + 0], 1.f + sc[c0 + 0], sh[c0 + 0]);
    o0.y = fmaf(v0.y * r * g[c0 + 1], 1.f + sc[c0 + 1], sh[c0 + 1]);
    o0.z = fmaf(v0.z * r * g[c0 + 2], 1.f + sc[c0 + 2], sh[c0 + 2]);
    o0.w = fmaf(v0.w * r * g[c0 + 3], 1.f + sc[c0 + 3], sh[c0 + 3]);
    o1.x = fmaf(v1.x * r * g[c1 + 0], 1.f + sc[c1 + 0], sh[c1 + 0]);
    o1.y = fmaf(v1.y * r * g[c1 + 1], 1.f + sc[c1 + 1], sh[c1 + 1]);
    o1.z = fmaf(v1.z * r * g[c1 + 2], 1.f + sc[c1 + 2], sh[c1 + 2]);
    o1.w = fmaf(v1.w * r * g[c1 + 3], 1.f + sc[c1 + 3], sh[c1 + 3]);
    long long base = row * DIM_;
    split_store4(o0, xh + base + c0, xl + base + c0);
    split_store4(o1, xh + base + c1, xl + base + c1);
}

__global__ void k_tsplit(const float* __restrict__ W, int KR, int NC,
                         __nv_bfloat16* __restrict__ Th,
                         __nv_bfloat16* __restrict__ Tl) {
    __shared__ float t[32][33];
    int c0 = blockIdx.x * 32, r0 = blockIdx.y * 32;
    for (int i = threadIdx.y; i < 32; i += 8)
        t[i][threadIdx.x] = W[(long long)(r0 + i) * NC + c0 + threadIdx.x];
    __syncthreads();
    for (int i = threadIdx.y; i < 32; i += 8) {
        float v = t[threadIdx.x][i];
        long long o = (long long)(c0 + i) * KR + r0 + threadIdx.x;
        __nv_bfloat16 h = __float2bfloat16(v);
        Th[o] = h;
        Tl[o] = __float2bfloat16(v - __bfloat162float(h));
    }
}

// ------------- generic GEMM + fused epilogues (unchanged from R13) ----------
#define CHUNK  32
#define ROWB   64
#define TILEB  (128 * ROWB)
#define STAGEB (4 * TILEB)
#define NSTAGE 3
#define GEMM_SMEM (NSTAGE * STAGEB)

__global__ void __launch_bounds__(256, 2)
gemm_bf16x3(const __nv_bfloat16* __restrict__ Ahi, const __nv_bfloat16* __restrict__ Alo,
            int lda,
            const __nv_bfloat16* __restrict__ Bhi, const __nv_bfloat16* __restrict__ Blo,
            int ldb,
            const __nv_bfloat16* __restrict__ CaddH, const __nv_bfloat16* __restrict__ CaddL,
            float* __restrict__ C, int ldc, int K,
            const float* __restrict__ gq, const float* __restrict__ gk,
            __nv_bfloat16* __restrict__ Qh, __nv_bfloat16* __restrict__ Ql,
            __nv_bfloat16* __restrict__ Vth, __nv_bfloat16* __restrict__ Vtl) {
    extern __shared__ char smem[];
    uint32_t sb = smem_u32(smem);
    int tid = threadIdx.x, wid = tid >> 5, lane = tid & 31;
    int warp_m = wid >> 2, warp_n = wid & 3;
    int row0 = blockIdx.y * 128, col0 = blockIdx.x * 128;

    float acc[4][4][4];
    #pragma unroll
    for (int i = 0; i < 4; i++)
        #pragma unroll
        for (int j = 0; j < 4; j++)
            #pragma unroll
            for (int r = 0; r < 4; r++) acc[i][j][r] = 0.f;

    int NC = K / CHUNK;
    auto load_stage = [&](int slot, int k0) {
        uint32_t base = sb + slot * STAGEB;
        #pragma unroll
        for (int t = 0; t < 4; t++) {
            const __nv_bfloat16* p = (t == 0) ? Ahi : (t == 1) ? Alo
                                   : (t == 2) ? Bhi : Blo;
            int r0g = (t < 2) ? row0 : col0;
            int ld  = (t < 2) ? lda : ldb;
            #pragma unroll
            for (int j = 0; j < 2; j++) {
                int id = tid + j * 256, rid = id >> 2, seg = id & 3;
                int sw = seg ^ ((rid >> 1) & 3);
                cp16(base + (uint32_t)t * TILEB + (uint32_t)(rid * ROWB + sw * 16),
                     p + (long long)(r0g + rid) * ld + k0 + seg * 8);
            }
        }
        cp_commit();
    };
    load_stage(0, 0);
    load_stage(1, CHUNK);

    int lr = lane & 15, cx = lane >> 4, swz = (lr >> 1) & 3;
    for (int i = 0; i < NC; i++) {
        if (i < NC - 1) cp_wait<1>(); else cp_wait<0>();
        __syncthreads();
        if (i + 2 < NC) load_stage((i + 2) % NSTAGE, (i + 2) * CHUNK);
        int slot = i % NSTAGE;
        uint32_t abase = sb + slot * STAGEB + (uint32_t)((warp_m * 64 + lr) * ROWB);
        uint32_t bbase = sb + slot * STAGEB + 2 * TILEB
                       + (uint32_t)((warp_n * 32 + lr) * ROWB);
        #pragma unroll
        for (int s = 0; s < 2; s++) {
            uint32_t co = (uint32_t)(((s << 1) | cx) ^ swz) << 4;
            uint32_t A1[4][4], A2[4][4], Bf[4][2];
            #pragma unroll
            for (int mi = 0; mi < 4; mi++)
                ldsm4(A1[mi][0], A1[mi][1], A1[mi][2], A1[mi][3],
                      abase + (uint32_t)(mi * 16 * ROWB) + co);
            #pragma unroll
            for (int np = 0; np < 2; np++) {
                uint32_t r0, r1, r2, r3;
                ldsm4(r0, r1, r2, r3, bbase + (uint32_t)(np * 16 * ROWB) + co);
                Bf[2 * np][0] = r0; Bf[2 * np][1] = r2;
                Bf[2 * np + 1][0] = r1; Bf[2 * np + 1][1] = r3;
            }
            #pragma unroll
            for (int mi = 0; mi < 4; mi++)
                #pragma unroll
                for (int ni = 0; ni < 4; ni++)
                    mma16816(acc[mi][ni], A1[mi], Bf[ni]);
            #pragma unroll
            for (int mi = 0; mi < 4; mi++)
                ldsm4(A2[mi][0], A2[mi][1], A2[mi][2], A2[mi][3],
                      abase + (uint32_t)(mi * 16 * ROWB) + co + TILEB);
            #pragma unroll
            for (int mi = 0; mi < 4; mi++)
                #pragma unroll
                for (int ni = 0; ni < 4; ni++)
                    mma16816(acc[mi][ni], A2[mi], Bf[ni]);
            #pragma unroll
            for (int np = 0; np < 2; np++) {
                uint32_t r0, r1, r2, r3;
                ldsm4(r0, r1, r2, r3,
                      bbase + (uint32_t)(np * 16 * ROWB) + co + TILEB);
                Bf[2 * np][0] = r0; Bf[2 * np][1] = r2;
                Bf[2 * np + 1][0] = r1; Bf[2 * np + 1][1] = r3;
            }
            #pragma unroll
            for (int mi = 0; mi < 4; mi++)
                #pragma unroll
                for (int ni = 0; ni < 4; ni++)
                    mma16816(acc[mi][ni], A1[mi], Bf[ni]);
        }
    }

    int mrow = row0 + warp_m * 64 + (lane >> 2);
    int ccol = col0 + warp_n * 32 + (lane & 3) * 2;

    if (Qh != nullptr) {
        if (col0 < 4096) {
            float* red = (float*)smem;
            __syncthreads();
            float ssum[4][2];
            #pragma unroll
            for (int mi = 0; mi < 4; mi++)
                #pragma unroll
                for (int h2 = 0; h2 < 2; h2++) {
                    float s = 0.f;
                    #pragma unroll
                    for (int ni = 0; ni < 4; ni++) {
                        float a0 = acc[mi][ni][h2 * 2];
                        float a1 = acc[mi][ni][h2 * 2 + 1];
                        s += a0 * a0 + a1 * a1;
                    }
                    s += __shfl_xor_sync(0xffffffffu, s, 1);
                    s += __shfl_xor_sync(0xffffffffu, s, 2);
                    ssum[mi][h2] = s;
                }
            if ((lane & 3) == 0) {
                int rl = warp_m * 64 + (lane >> 2);
                #pragma unroll
                for (int mi = 0; mi < 4; mi++)
                    #pragma unroll
                    for (int h2 = 0; h2 < 2; h2++)
                        red[(rl + mi * 16 + h2 * 8) * 4 + warp_n] = ssum[mi][h2];
            }
            __syncthreads();
            const float* gv = (col0 < 2048) ? gq : gk;
            float g8[4][2];
            #pragma unroll
            for (int ni = 0; ni < 4; ni++) {
                g8[ni][0] = gv[((ccol + ni * 8) & 127)];
                g8[ni][1] = gv[((ccol + ni * 8) & 127) + 1];
            }
            #pragma unroll
            for (int mi = 0; mi < 4; mi++)
                #pragma unroll
                for (int h2 = 0; h2 < 2; h2++) {
                    int rl = warp_m * 64 + (lane >> 2) + mi * 16 + h2 * 8;
                    float s = red[rl * 4 + 0] + red[rl * 4 + 1]
                            + red[rl * 4 + 2] + red[rl * 4 + 3];
                    float r = rsqrtf(s * (1.f / DH_) + 1e-6f);
                    long long o = (long long)(row0 + rl) * (2 * DIM_) + ccol;
                    #pragma unroll
                    for (int ni = 0; ni < 4; ni++) {
                        float v0 = acc[mi][ni][h2 * 2]     * r * g8[ni][0];
                        float v1 = acc[mi][ni][h2 * 2 + 1] * r * g8[ni][1];
                        *(uint32_t*)(Qh + o + ni * 8) = pack_hi2(v0, v1);
                        *(uint32_t*)(Ql + o + ni * 8) = pack_lo2(v0, v1);
                    }
                }
        } else {
            float* T = (float*)smem;
            __syncthreads();
            int lcol = warp_n * 32 + (lane & 3) * 2;
            #pragma unroll
            for (int mi = 0; mi < 4; mi++)
                #pragma unroll
                for (int h2 = 0; h2 < 2; h2++) {
                    int rl = warp_m * 64 + (lane >> 2) + mi * 16 + h2 * 8;
                    #pragma unroll
                    for (int ni = 0; ni < 4; ni++) {
                        T[rl * 129 + lcol + ni * 8]     = acc[mi][ni][h2 * 2];
                        T[rl * 129 + lcol + ni * 8 + 1] = acc[mi][ni][h2 * 2 + 1];
                    }
                }
            __syncthreads();
            int b = row0 >> 11;
            int h = (col0 - 4096) >> 7;
            int tok0g = row0 & 2047;
            long long zoff = (long long)(b * 16 + h) * DH_ * N_;
            #pragma unroll
            for (int k = 0; k < 32; k++) {
                int p = tid + k * 256;
                int d = p >> 6;
                int tk = (p & 63) * 2;
                float v0 = T[tk * 129 + d];
                float v1 = T[(tk + 1) * 129 + d];
                long long o = zoff + (long long)d * N_ + tok0g + tk;
                *(uint32_t*)(Vth + o) = pack_hi2(v0, v1);
                *(uint32_t*)(Vtl + o) = pack_lo2(v0, v1);
            }
        }
        return;
    }

    bool addc = (CaddH != nullptr);
    #pragma unroll
    for (int mi = 0; mi < 4; mi++)
        #pragma unroll
        for (int ni = 0; ni < 4; ni++) {
            long long o0 = (long long)(mrow + mi * 16) * ldc + ccol + ni * 8;
            long long o1 = o0 + 8LL * ldc;
            float2 v0 = make_float2(acc[mi][ni][0], acc[mi][ni][1]);
            float2 v1 = make_float2(acc[mi][ni][2], acc[mi][ni][3]);
            if (addc) {
                float2 h0 = unp2(*(const uint32_t*)(CaddH + o0));
                float2 l0 = unp2(*(const uint32_t*)(CaddL + o0));
                float2 h1 = unp2(*(const uint32_t*)(CaddH + o1));
                float2 l1 = unp2(*(const uint32_t*)(CaddL + o1));
                v0.x += h0.x + l0.x; v0.y += h0.y + l0.y;
                v1.x += h1.x + l1.x; v1.y += h1.y + l1.y;
            }
            *(float2*)(C + o0) = v0;
            *(float2*)(C + o1) = v1;
        }
}

// ------------- flash attention: early dual prefetch, 10 syncs/j -------------
#define FQ_    0
#define FKV_   32768
#define FP_    65536
#define F_RM   98304
#define F_RS   99328
#define F_M    100352
#define F_L    100608
#define FLASH_SMEM 100864

__global__ void __launch_bounds__(256, 2)
flash_attn(const __nv_bfloat16* __restrict__ qkh, const __nv_bfloat16* __restrict__ qkl,
           const __nv_bfloat16* __restrict__ vTh, const __nv_bfloat16* __restrict__ vTl,
           __nv_bfloat16* __restrict__ oh, __nv_bfloat16* __restrict__ ol) {
    extern __shared__ char smem[];
    uint32_t sb = smem_u32(smem);
    int tid = threadIdx.x, lane = tid & 31, wid = tid >> 5;
    int fm = wid >> 2, fn = wid & 3;
    int lr = lane & 15, cx = lane >> 4, swz = (lr >> 1) & 3;
    int qt = blockIdx.x, z = blockIdx.y, b = z >> 4, h = z & 15;
    long long qrow0 = (long long)b * N_ + qt * 64;
    long long krow0 = (long long)b * N_;
    int hcol = h * DH_;
    long long zoff = (long long)z * DH_ * N_;
    const float SCALE = 0.08838834764831845f;

    float* RM = (float*)(smem + F_RM);
    float* RS = (float*)(smem + F_RS);
    float* Mv = (float*)(smem + F_M);
    float* Lv = (float*)(smem + F_L);
    if (tid < 64) { Mv[tid] = -1e30f; Lv[tid] = 0.f; }

    float oacc[2][4][4];
    #pragma unroll
    for (int mi = 0; mi < 2; mi++)
        #pragma unroll
        for (int ni = 0; ni < 4; ni++)
            #pragma unroll
            for (int e = 0; e < 4; e++) oacc[mi][ni][e] = 0.f;

    {
        int rid = tid >> 2, seg = tid & 3;
        int sw = seg ^ ((rid >> 1) & 3);
        #pragma unroll
        for (int c = 0; c < 4; c++) {
            long long off = (qrow0 + rid) * (2LL * DIM_) + hcol + c * 32 + seg * 8;
            uint32_t d = sb + FQ_ + (uint32_t)(c * 8192 + rid * 64 + sw * 16);
            cp16(d, qkh + off);
            cp16(d + 4096, qkl + off);
        }
        cp_commit();
    }

    auto load_k = [&](int st, int c, int j) {
        #pragma unroll
        for (int t = 0; t < 2; t++) {
            int id = tid + t * 256, rid = id >> 2, seg = id & 3;
            int sw = seg ^ ((rid >> 1) & 3);
            long long off = (krow0 + j * 128 + rid) * (2LL * DIM_)
                          + hcol + DIM_ + c * 32 + seg * 8;
            uint32_t d = sb + FKV_ + (uint32_t)(st * 16384 + rid * 64 + sw * 16);
            cp16(d, qkh + off);
            cp16(d + 8192, qkl + off);
        }
        cp_commit();
    };
    auto load_v = [&](int st, int c, int j) {
        #pragma unroll
        for (int t = 0; t < 2; t++) {
            int id = tid + t * 256, rid = id >> 2, seg = id & 3;
            int sw = seg ^ ((rid >> 1) & 3);
            long long off = zoff + (long long)rid * N_ + j * 128 + c * 32 + seg * 8;
            uint32_t d = sb + FKV_ + (uint32_t)(st * 16384 + rid * 64 + sw * 16);
            cp16(d, vTh + off);
            cp16(d + 8192, vTl + off);
        }
        cp_commit();
    };

    int rbase = fm * 32 + (lane >> 2);
    int cq = (lane & 3) * 2;

    for (int j = 0; j < 16; j++) {
        float sacc[2][4][4];
        #pragma unroll
        for (int mi = 0; mi < 2; mi++)
            #pragma unroll
            for (int ni = 0; ni < 4; ni++)
                #pragma unroll
                for (int e = 0; e < 4; e++) sacc[mi][ni][e] = 0.f;

        // both K stages prefetched up front (stage 1 freed by trailing sync)
        load_k(0, 0, j);
        load_k(1, 1, j);
        for (int c = 0; c < 4; c++) {
            if (c == 0) cp_wait<1>(); else cp_wait<0>();
            __syncthreads();
            if (c >= 1 && c < 3) load_k((c + 1) & 1, c + 1, j);
            uint32_t abase = sb + FQ_ + (uint32_t)(c * 8192 + (fm * 32 + lr) * 64);
            uint32_t bbase = sb + FKV_ + (uint32_t)(((c & 1) * 16384)
                           + (fn * 32 + lr) * 64);
            #pragma unroll
            for (int s = 0; s < 2; s++) {
                uint32_t co = (uint32_t)(((s << 1) | cx) ^ swz) << 4;
                uint32_t A1[2][4], A2[2][4], Bf[4][2];
                #pragma unroll
                for (int mi = 0; mi < 2; mi++)
                    ldsm4(A1[mi][0], A1[mi][1], A1[mi][2], A1[mi][3],
                          abase + (uint32_t)(mi * 1024) + co);
                #pragma unroll
                for (int np = 0; np < 2; np++) {
                    uint32_t r0, r1, r2, r3;
                    ldsm4(r0, r1, r2, r3, bbase + (uint32_t)(np * 1024) + co);
                    Bf[2 * np][0] = r0; Bf[2 * np][1] = r2;
                    Bf[2 * np + 1][0] = r1; Bf[2 * np + 1][1] = r3;
                }
                #pragma unroll
                for (int mi = 0; mi < 2; mi++)
                    #pragma unroll
                    for (int ni = 0; ni < 4; ni++)
                        mma16816(sacc[mi][ni], A1[mi], Bf[ni]);
                #pragma unroll
                for (int mi = 0; mi < 2; mi++)
                    ldsm4(A2[mi][0], A2[mi][1], A2[mi][2], A2[mi][3],
                          abase + (uint32_t)(mi * 1024) + co + 4096);
                #pragma unroll
                for (int mi = 0; mi < 2; mi++)
                    #pragma unroll
                    for (int ni = 0; ni < 4; ni++)
                        mma16816(sacc[mi][ni], A2[mi], Bf[ni]);
                #pragma unroll
                for (int np = 0; np < 2; np++) {
                    uint32_t r0, r1, r2, r3;
                    ldsm4(r0, r1, r2, r3, bbase + (uint32_t)(np * 1024) + co + 8192);
                    Bf[2 * np][0] = r0; Bf[2 * np][1] = r2;
                    Bf[2 * np + 1][0] = r1; Bf[2 * np + 1][1] = r3;
                }
                #pragma unroll
                for (int mi = 0; mi < 2; mi++)
                    #pragma unroll
                    for (int ni = 0; ni < 4; ni++)
                        mma16816(sacc[mi][ni], A1[mi], Bf[ni]);
            }
        }

        float rmax[2][2];
        #pragma unroll
        for (int mi = 0; mi < 2; mi++)
            #pragma unroll
            for (int h2 = 0; h2 < 2; h2++) {
                float m = -1e30f;
                #pragma unroll
                for (int ni = 0; ni < 4; ni++) {
                    sacc[mi][ni][h2 * 2]     *= SCALE;
                    sacc[mi][ni][h2 * 2 + 1] *= SCALE;
                    m = fmaxf(m, fmaxf(sacc[mi][ni][h2 * 2], sacc[mi][ni][h2 * 2 + 1]));
                }
                #pragma unroll
                for (int o = 1; o <= 2; o <<= 1)
                    m = fmaxf(m, __shfl_xor_sync(0xffffffffu, m, o));
                rmax[mi][h2] = m;
            }
        if ((lane & 3) == 0)
            #pragma unroll
            for (int mi = 0; mi < 2; mi++)
                #pragma unroll
                for (int h2 = 0; h2 < 2; h2++)
                    RM[(rbase + mi * 16 + h2 * 8) * 4 + fn] = rmax[mi][h2];
        __syncthreads();

        // both V stages prefetched here: overlap the whole softmax phase
        load_v(0, 0, j);
        load_v(1, 1, j);

        float mnew[2][2], fact[2][2], rsum[2][2];
        #pragma unroll
        for (int mi = 0; mi < 2; mi++)
            #pragma unroll
            for (int h2 = 0; h2 < 2; h2++) {
                int r = rbase + mi * 16 + h2 * 8;
                float bm = fmaxf(fmaxf(RM[r * 4 + 0], RM[r * 4 + 1]),
                                 fmaxf(RM[r * 4 + 2], RM[r * 4 + 3]));
                float mo = Mv[r];
                float mn = fmaxf(mo, bm);
                mnew[mi][h2] = mn;
                fact[mi][h2] = __expf(mo - mn);
                rsum[mi][h2] = 0.f;
            }
        #pragma unroll
        for (int mi = 0; mi < 2; mi++)
            #pragma unroll
            for (int ni = 0; ni < 4; ni++)
                #pragma unroll
                for (int e = 0; e < 4; e++) {
                    int h2 = e >> 1;
                    oacc[mi][ni][e] *= fact[mi][h2];
                    float p = __expf(sacc[mi][ni][e] - mnew[mi][h2]);
                    sacc[mi][ni][e] = p;
                    rsum[mi][h2] += p;
                }
        #pragma unroll
        for (int o = 1; o <= 2; o <<= 1)
            #pragma unroll
            for (int mi = 0; mi < 2; mi++)
                #pragma unroll
                for (int h2 = 0; h2 < 2; h2++)
                    rsum[mi][h2] += __shfl_xor_sync(0xffffffffu, rsum[mi][h2], o);
        if ((lane & 3) == 0)
            #pragma unroll
            for (int mi = 0; mi < 2; mi++)
                #pragma unroll
                for (int h2 = 0; h2 < 2; h2++)
                    RS[(rbase + mi * 16 + h2 * 8) * 4 + fn] = rsum[mi][h2];
        #pragma unroll
        for (int mi = 0; mi < 2; mi++)
            #pragma unroll
            for (int h2 = 0; h2 < 2; h2++) {
                int rl = rbase + mi * 16 + h2 * 8;
                int key = (rl >> 1) & 3;
                uint32_t rowb = sb + FP_ + (uint32_t)(fn * 4096) + (uint32_t)(rl * 64);
                #pragma unroll
                for (int ni = 0; ni < 4; ni++) {
                    int cc = cq + ni * 8;
                    uint32_t boff = rowb
                        + (uint32_t)((((cc >> 3) ^ key) << 4) + (cc & 7) * 2);
                    float p0 = sacc[mi][ni][h2 * 2];
                    float p1 = sacc[mi][ni][h2 * 2 + 1];
                    st32(boff,         pack_hi2(p0, p1));
                    st32(boff + 16384, pack_lo2(p0, p1));
                }
            }
        // no sync here: V-loop c=0 barrier orders P/RS stores for all warps

        for (int c = 0; c < 4; c++) {
            if (c == 0) cp_wait<1>(); else cp_wait<0>();
            __syncthreads();
            if (c == 0) {
                if (fn == 0 && (lane & 3) == 0)
                    #pragma unroll
                    for (int mi = 0; mi < 2; mi++)
                        #pragma unroll
                        for (int h2 = 0; h2 < 2; h2++) {
                            int r = rbase + mi * 16 + h2 * 8;
                            Mv[r] = mnew[mi][h2];
                            Lv[r] = Lv[r] * fact[mi][h2]
                                  + RS[r * 4] + RS[r * 4 + 1]
                                  + RS[r * 4 + 2] + RS[r * 4 + 3];
                        }
            }
            if (c >= 1 && c < 3) load_v((c + 1) & 1, c + 1, j);
            uint32_t pbase = sb + FP_ + (uint32_t)(c * 4096)
                           + (uint32_t)((fm * 32 + lr) * 64);
            uint32_t vbase = sb + FKV_ + (uint32_t)(((c & 1) * 16384)
                           + (fn * 32 + lr) * 64);
            #pragma unroll
            for (int s = 0; s < 2; s++) {
                uint32_t co = (uint32_t)(((s << 1) | cx) ^ swz) << 4;
                uint32_t A1[2][4], A2[2][4], Bf[4][2];
                #pragma unroll
                for (int mi = 0; mi < 2; mi++)
                    ldsm4(A1[mi][0], A1[mi][1], A1[mi][2], A1[mi][3],
                          pbase + (uint32_t)(mi * 1024) + co);
                #pragma unroll
                for (int np = 0; np < 2; np++) {
                    uint32_t r0, r1, r2, r3;
                    ldsm4(r0, r1, r2, r3, vbase + (uint32_t)(np * 1024) + co);
                    Bf[2 * np][0] = r0; Bf[2 * np][1] = r2;
                    Bf[2 * np + 1][0] = r1; Bf[2 * np + 1][1] = r3;
                }
                #pragma unroll
                for (int mi = 0; mi < 2; mi++)
                    #pragma unroll
                    for (int ni = 0; ni < 4; ni++)
                        mma16816(oacc[mi][ni], A1[mi], Bf[ni]);
                #pragma unroll
                for (int mi = 0; mi < 2; mi++)
                    ldsm4(A2[mi][0], A2[mi][1], A2[mi][2], A2[mi][3],
                          pbase + (uint32_t)(mi * 1024) + co + 16384);
                #pragma unroll
                for (int mi = 0; mi < 2; mi++)
                    #pragma unroll
                    for (int ni = 0; ni < 4; ni++)
                        mma16816(oacc[mi][ni], A2[mi], Bf[ni]);
                #pragma unroll
                for (int np = 0; np < 2; np++) {
                    uint32_t r0, r1, r2, r3;
                    ldsm4(r0, r1, r2, r3, vbase + (uint32_t)(np * 1024) + co + 8192);
                    Bf[2 * np][0] = r0; Bf[2 * np][1] = r2;
                    Bf[2 * np + 1][0] = r1; Bf[2 * np + 1][1] = r3;
                }
                #pragma unroll
                for (int mi = 0; mi < 2; mi++)
                    #pragma unroll
                    for (int ni = 0; ni < 4; ni++)
                        mma16816(oacc[mi][ni], A1[mi], Bf[ni]);
            }
        }
        __syncthreads();   // stage-1/P reuse guard for next j's early loads
    }

    #pragma unroll
    for (int mi = 0; mi < 2; mi++)
        #pragma unroll
        for (int h2 = 0; h2 < 2; h2++) {
            int rl = rbase + mi * 16 + h2 * 8;
            float li = 1.f / Lv[rl];
            long long row = (qrow0 + rl) * (long long)DIM_ + hcol + fn * 32;
            #pragma unroll
            for (int ni = 0; ni < 4; ni++) {
                float v0 = oacc[mi][ni][h2 * 2] * li;
                float v1 = oacc[mi][ni][h2 * 2 + 1] * li;
                long long o = row + cq + ni * 8;
                *(uint32_t*)(oh + o) = pack_hi2(v0, v1);
                *(uint32_t*)(ol + o) = pack_lo2(v0, v1);
            }
        }
}

// ---------------------------------------------------------------------------
extern "C" void kernel_launch(void* const* d_in, const int* in_sizes, int n_in,
                              void* d_out, int out_size) {
    const float* x      = (const float*)d_in[0];
    const float* emb    = (const float*)d_in[1];
    const float* W_emb  = (const float*)d_in[2];
    const float* b_emb  = (const float*)d_in[3];
    const float* g_norm = (const float*)d_in[4];
    const float* W_qkv  = (const float*)d_in[5];
    const float* g_q    = (const float*)d_in[6];
    const float* g_k    = (const float*)d_in[7];
    const float* W_out  = (const float*)d_in[8];
    float* out = (float*)d_out;
    (void)in_sizes; (void)n_in; (void)out_size;

    float *ss;
    __nv_bfloat16 *xnh, *xnl, *wqTh, *wqTl, *woTh, *woTl;
    __nv_bfloat16 *qkh, *qkl, *vTh, *vTl, *oh, *ol;
    cudaGetSymbolAddress((void**)&ss,   g_ss);
    cudaGetSymbolAddress((void**)&xnh,  g_xnh);
    cudaGetSymbolAddress((void**)&xnl,  g_xnl);
    cudaGetSymbolAddress((void**)&wqTh, g_wqTh);
    cudaGetSymbolAddress((void**)&wqTl, g_wqTl);
    cudaGetSymbolAddress((void**)&woTh, g_woTh);
    cudaGetSymbolAddress((void**)&woTl, g_woTl);
    cudaGetSymbolAddress((void**)&qkh,  g_qkh);
    cudaGetSymbolAddress((void**)&qkl,  g_qkl);
    cudaGetSymbolAddress((void**)&vTh,  g_vTh);
    cudaGetSymbolAddress((void**)&vTl,  g_vTl);
    cudaGetSymbolAddress((void**)&oh,   g_oh);
    cudaGetSymbolAddress((void**)&ol,   g_ol);

    cudaFuncSetAttribute(gemm_bf16x3,
                         cudaFuncAttributeMaxDynamicSharedMemorySize, GEMM_SMEM);
    cudaFuncSetAttribute(flash_attn,
                         cudaFuncAttributeMaxDynamicSharedMemorySize, FLASH_SMEM);

    k_scale_shift<<<dim3((2 * DIM_) / 256, B_), 256>>>(emb, W_emb, b_emb, ss);
    k_xnorm<<<TOK_, 256>>>(x, g_norm, ss, xnh, xnl);
    k_tsplit<<<dim3(QKVC_ / 32, DIM_ / 32), dim3(32, 8)>>>(W_qkv, DIM_, QKVC_, wqTh, wqTl);
    gemm_bf16x3<<<dim3(QKVC_ / 128, TOK_ / 128, 1), 256, GEMM_SMEM>>>(
        xnh, xnl, DIM_, wqTh, wqTl, DIM_, nullptr, nullptr, nullptr, 0, DIM_,
        g_q, g_k, qkh, qkl, vTh, vTl);
    flash_attn<<<dim3(N_ / 64, BH_), 256, FLASH_SMEM>>>(
        qkh, qkl, vTh, vTl, oh, ol);
    k_tsplit<<<dim3(DIM_ / 32, DIM_ / 32), dim3(32, 8)>>>(W_out, DIM_, DIM_, woTh, woTl);
    gemm_bf16x3<<<dim3(DIM_ / 128, TOK_ / 128, 1), 256, GEMM_SMEM>>>(
        oh, ol, DIM_, woTh, woTl, DIM_, oh, ol, out, DIM_, DIM_,
        nullptr, nullptr, nullptr, nullptr, nullptr, nullptr);
}

// round 16
// speedup vs baseline: 1.0072x; 1.0072x over previous
#include <cuda_runtime.h>
#include <cuda_bf16.h>
#include <cstdint>

#define B_     4
#define N_     2048
#define DIM_   2048
#define H_     16
#define DH_    128
#define TOK_   (B_ * N_)
#define QKVC_  (3 * DIM_)
#define BH_    (B_ * H_)

__device__ float          g_ss[B_ * 2 * DIM_];
__device__ __nv_bfloat16  g_xnh[(long long)TOK_ * DIM_];
__device__ __nv_bfloat16  g_xnl[(long long)TOK_ * DIM_];
__device__ __nv_bfloat16  g_wqTh[(long long)QKVC_ * DIM_];
__device__ __nv_bfloat16  g_wqTl[(long long)QKVC_ * DIM_];
__device__ __nv_bfloat16  g_woTh[(long long)DIM_ * DIM_];
__device__ __nv_bfloat16  g_woTl[(long long)DIM_ * DIM_];
__device__ __nv_bfloat16  g_qkh[(long long)TOK_ * 2 * DIM_];
__device__ __nv_bfloat16  g_qkl[(long long)TOK_ * 2 * DIM_];
__device__ __nv_bfloat16  g_vTh[(long long)BH_ * DH_ * N_];
__device__ __nv_bfloat16  g_vTl[(long long)BH_ * DH_ * N_];
__device__ __nv_bfloat16  g_oh[(long long)TOK_ * DIM_];
__device__ __nv_bfloat16  g_ol[(long long)TOK_ * DIM_];

__device__ __forceinline__ uint32_t smem_u32(const void* p) {
    uint32_t a;
    asm("{ .reg .u64 t; cvta.to.shared.u64 t, %1; cvt.u32.u64 %0, t; }"
        : "=r"(a) : "l"(p));
    return a;
}
__device__ __forceinline__ void cp16(uint32_t dst, const void* src) {
    asm volatile("cp.async.cg.shared.global [%0], [%1], 16;"
                 :: "r"(dst), "l"(__cvta_generic_to_global(src)));
}
__device__ __forceinline__ void cp_commit() {
    asm volatile("cp.async.commit_group;" ::: "memory");
}
template <int NN>
__device__ __forceinline__ void cp_wait() {
    asm volatile("cp.async.wait_group %0;" :: "n"(NN) : "memory");
}
__device__ __forceinline__ void ldsm4(uint32_t& r0, uint32_t& r1,
                                      uint32_t& r2, uint32_t& r3, uint32_t a) {
    asm volatile("ldmatrix.sync.aligned.m8n8.x4.shared.b16 {%0,%1,%2,%3}, [%4];"
                 : "=r"(r0), "=r"(r1), "=r"(r2), "=r"(r3) : "r"(a));
}
__device__ __forceinline__ void mma16816(float* d, const uint32_t* a,
                                         const uint32_t* b) {
    asm volatile(
        "mma.sync.aligned.m16n8k16.row.col.f32.bf16.bf16.f32 "
        "{%0,%1,%2,%3}, {%4,%5,%6,%7}, {%8,%9}, {%0,%1,%2,%3};"
        : "+f"(d[0]), "+f"(d[1]), "+f"(d[2]), "+f"(d[3])
        : "r"(a[0]), "r"(a[1]), "r"(a[2]), "r"(a[3]), "r"(b[0]), "r"(b[1]));
}
__device__ __forceinline__ void st32(uint32_t a, uint32_t v) {
    asm volatile("st.shared.b32 [%0], %1;" :: "r"(a), "r"(v) : "memory");
}
__device__ __forceinline__ void split_store4(float4 v,
                                             __nv_bfloat16* __restrict__ hi,
                                             __nv_bfloat16* __restrict__ lo) {
    __nv_bfloat16 h[4], l[4];
    float f[4] = {v.x, v.y, v.z, v.w};
    #pragma unroll
    for (int i = 0; i < 4; i++) {
        h[i] = __float2bfloat16(f[i]);
        l[i] = __float2bfloat16(f[i] - __bfloat162float(h[i]));
    }
    *(uint2*)hi = *(const uint2*)h;
    *(uint2*)lo = *(const uint2*)l;
}
__device__ __forceinline__ uint32_t pack_hi2(float a, float b) {
    __nv_bfloat16 h[2] = {__float2bfloat16(a), __float2bfloat16(b)};
    return *(const uint32_t*)h;
}
__device__ __forceinline__ uint32_t pack_lo2(float a, float b) {
    __nv_bfloat16 ha = __float2bfloat16(a), hb = __float2bfloat16(b);
    __nv_bfloat16 l[2] = {__float2bfloat16(a - __bfloat162float(ha)),
                          __float2bfloat16(b - __bfloat162float(hb))};
    return *(const uint32_t*)l;
}
__device__ __forceinline__ float2 unp2(uint32_t u) {
    __nv_bfloat16* p = (__nv_bfloat16*)&u;
    return make_float2(__bfloat162float(p[0]), __bfloat162float(p[1]));
}
__device__ __forceinline__ float blk_sum256(float v) {
    __shared__ float red[8];
    __shared__ float tot;
    #pragma unroll
    for (int o = 16; o > 0; o >>= 1) v += __shfl_xor_sync(0xffffffffu, v, o);
    if ((threadIdx.x & 31) == 0) red[threadIdx.x >> 5] = v;
    __syncthreads();
    if (threadIdx.x == 0) {
        float s = 0.f;
        #pragma unroll
        for (int i = 0; i < 8; i++) s += red[i];
        tot = s;
    }
    __syncthreads();
    return tot;
}

__global__ void k_scale_shift(const float* __restrict__ emb,
                              const float* __restrict__ W,
                              const float* __restrict__ bias,
                              float* __restrict__ ss) {
    int c = blockIdx.x * 256 + threadIdx.x;
    int b = blockIdx.y;
    const float* e = emb + b * DIM_;
    float acc = bias[c];
    const float* wp = W + c;
    #pragma unroll 8
    for (int k = 0; k < DIM_; k++)
        acc = fmaf(e[k], wp[(long long)k * (2 * DIM_)], acc);
    ss[b * (2 * DIM_) + c] = acc;
}

__global__ void k_xnorm(const float* __restrict__ x,
                        const float* __restrict__ g,
                        const float* __restrict__ ss,
                        __nv_bfloat16* __restrict__ xh,
                        __nv_bfloat16* __restrict__ xl) {
    long long row = blockIdx.x;
    int b = (int)(row >> 11);
    const float4* xr = (const float4*)(x + row * DIM_);
    float4 v0 = xr[threadIdx.x];
    float4 v1 = xr[threadIdx.x + 256];
    float s = v0.x * v0.x + v0.y * v0.y + v0.z * v0.z + v0.w * v0.w
            + v1.x * v1.x + v1.y * v1.y + v1.z * v1.z + v1.w * v1.w;
    s = blk_sum256(s);
    float r = rsqrtf(s * (1.f / DIM_) + 1e-6f);
    const float* sc = ss + b * (2 * DIM_);
    const float* sh = sc + DIM_;
    int c0 = threadIdx.x * 4, c1 = (threadIdx.x + 256) * 4;
    float4 o0, o1;
    o0.x = fmaf(v0.x * r * g[c0 + 0], 1.f + sc[c0 + 0], sh[c0 + 0]);
    o0.y = fmaf(v0.y * r * g[c0 + 1], 1.f + sc[c0 + 1], sh[c0 + 1]);
    o0.z = fmaf(v0.z * r * g[c0 + 2], 1.f + sc[c0 + 2], sh[c0 + 2]);
    o0.w = fmaf(v0.w * r * g[c0 + 3], 1.f + sc[c0 + 3], sh[c0 + 3]);
    o1.x = fmaf(v1.x * r * g[c1 + 0], 1.f + sc[c1 + 0], sh[c1 + 0]);
    o1.y = fmaf(v1.y * r * g[c1 + 1], 1.f + sc[c1 + 1], sh[c1 + 1]);
    o1.z = fmaf(v1.z * r * g[c1 + 2], 1.f + sc[c1 + 2], sh[c1 + 2]);
    o1.w = fmaf(v1.w * r * g[c1 + 3], 1.f + sc[c1 + 3], sh[c1 + 3]);
    long long base = row * DIM_;
    split_store4(o0, xh + base + c0, xl + base + c0);
    split_store4(o1, xh + base + c1, xl + base + c1);
}

__global__ void k_tsplit(const float* __restrict__ W, int KR, int NC,
                         __nv_bfloat16* __restrict__ Th,
                         __nv_bfloat16* __restrict__ Tl) {
    __shared__ float t[32][33];
    int c0 = blockIdx.x * 32, r0 = blockIdx.y * 32;
    for (int i = threadIdx.y; i < 32; i += 8)
        t[i][threadIdx.x] = W[(long long)(r0 + i) * NC + c0 + threadIdx.x];
    __syncthreads();
    for (int i = threadIdx.y; i < 32; i += 8) {
        float v = t[threadIdx.x][i];
        long long o = (long long)(c0 + i) * KR + r0 + threadIdx.x;
        __nv_bfloat16 h = __float2bfloat16(v);
        Th[o] = h;
        Tl[o] = __float2bfloat16(v - __bfloat162float(h));
    }
}

// ------------- generic GEMM + fused epilogues -------------------------------
#define CHUNK  32
#define ROWB   64
#define TILEB  (128 * ROWB)
#define STAGEB (4 * TILEB)
#define NSTAGE 3
#define GEMM_SMEM (NSTAGE * STAGEB)

__global__ void __launch_bounds__(256, 2)
gemm_bf16x3(const __nv_bfloat16* __restrict__ Ahi, const __nv_bfloat16* __restrict__ Alo,
            int lda,
            const __nv_bfloat16* __restrict__ Bhi, const __nv_bfloat16* __restrict__ Blo,
            int ldb,
            const __nv_bfloat16* __restrict__ CaddH, const __nv_bfloat16* __restrict__ CaddL,
            float* __restrict__ C, int ldc, int K,
            const float* __restrict__ gq, const float* __restrict__ gk,
            __nv_bfloat16* __restrict__ Qh, __nv_bfloat16* __restrict__ Ql,
            __nv_bfloat16* __restrict__ Vth, __nv_bfloat16* __restrict__ Vtl) {
    extern __shared__ char smem[];
    uint32_t sb = smem_u32(smem);
    int tid = threadIdx.x, wid = tid >> 5, lane = tid & 31;
    int warp_m = wid >> 2, warp_n = wid & 3;
    int row0 = blockIdx.y * 128, col0 = blockIdx.x * 128;

    float acc[4][4][4];
    #pragma unroll
    for (int i = 0; i < 4; i++)
        #pragma unroll
        for (int j = 0; j < 4; j++)
            #pragma unroll
            for (int r = 0; r < 4; r++) acc[i][j][r] = 0.f;

    int NC = K / CHUNK;
    auto load_stage = [&](int slot, int k0) {
        uint32_t base = sb + slot * STAGEB;
        #pragma unroll
        for (int t = 0; t < 4; t++) {
            const __nv_bfloat16* p = (t == 0) ? Ahi : (t == 1) ? Alo
                                   : (t == 2) ? Bhi : Blo;
            int r0g = (t < 2) ? row0 : col0;
            int ld  = (t < 2) ? lda : ldb;
            #pragma unroll
            for (int j = 0; j < 2; j++) {
                int id = tid + j * 256, rid = id >> 2, seg = id & 3;
                int sw = seg ^ ((rid >> 1) & 3);
                cp16(base + (uint32_t)t * TILEB + (uint32_t)(rid * ROWB + sw * 16),
                     p + (long long)(r0g + rid) * ld + k0 + seg * 8);
            }
        }
        cp_commit();
    };
    load_stage(0, 0);
    load_stage(1, CHUNK);

    int lr = lane & 15, cx = lane >> 4, swz = (lr >> 1) & 3;
    for (int i = 0; i < NC; i++) {
        if (i < NC - 1) cp_wait<1>(); else cp_wait<0>();
        __syncthreads();
        if (i + 2 < NC) load_stage((i + 2) % NSTAGE, (i + 2) * CHUNK);
        int slot = i % NSTAGE;
        uint32_t abase = sb + slot * STAGEB + (uint32_t)((warp_m * 64 + lr) * ROWB);
        uint32_t bbase = sb + slot * STAGEB + 2 * TILEB
                       + (uint32_t)((warp_n * 32 + lr) * ROWB);
        #pragma unroll
        for (int s = 0; s < 2; s++) {
            uint32_t co = (uint32_t)(((s << 1) | cx) ^ swz) << 4;
            uint32_t A1[4][4], A2[4][4], Bf[4][2];
            #pragma unroll
            for (int mi = 0; mi < 4; mi++)
                ldsm4(A1[mi][0], A1[mi][1], A1[mi][2], A1[mi][3],
                      abase + (uint32_t)(mi * 16 * ROWB) + co);
            #pragma unroll
            for (int np = 0; np < 2; np++) {
                uint32_t r0, r1, r2, r3;
                ldsm4(r0, r1, r2, r3, bbase + (uint32_t)(np * 16 * ROWB) + co);
                Bf[2 * np][0] = r0; Bf[2 * np][1] = r2;
                Bf[2 * np + 1][0] = r1; Bf[2 * np + 1][1] = r3;
            }
            #pragma unroll
            for (int mi = 0; mi < 4; mi++)
                #pragma unroll
                for (int ni = 0; ni < 4; ni++)
                    mma16816(acc[mi][ni], A1[mi], Bf[ni]);
            #pragma unroll
            for (int mi = 0; mi < 4; mi++)
                ldsm4(A2[mi][0], A2[mi][1], A2[mi][2], A2[mi][3],
                      abase + (uint32_t)(mi * 16 * ROWB) + co + TILEB);
            #pragma unroll
            for (int mi = 0; mi < 4; mi++)
                #pragma unroll
                for (int ni = 0; ni < 4; ni++)
                    mma16816(acc[mi][ni], A2[mi], Bf[ni]);
            #pragma unroll
            for (int np = 0; np < 2; np++) {
                uint32_t r0, r1, r2, r3;
                ldsm4(r0, r1, r2, r3,
                      bbase + (uint32_t)(np * 16 * ROWB) + co + TILEB);
                Bf[2 * np][0] = r0; Bf[2 * np][1] = r2;
                Bf[2 * np + 1][0] = r1; Bf[2 * np + 1][1] = r3;
            }
            #pragma unroll
            for (int mi = 0; mi < 4; mi++)
                #pragma unroll
                for (int ni = 0; ni < 4; ni++)
                    mma16816(acc[mi][ni], A1[mi], Bf[ni]);
        }
    }

    int mrow = row0 + warp_m * 64 + (lane >> 2);
    int ccol = col0 + warp_n * 32 + (lane & 3) * 2;

    if (Qh != nullptr) {
        if (col0 < 4096) {
            float* red = (float*)smem;
            __syncthreads();
            float ssum[4][2];
            #pragma unroll
            for (int mi = 0; mi < 4; mi++)
                #pragma unroll
                for (int h2 = 0; h2 < 2; h2++) {
                    float s = 0.f;
                    #pragma unroll
                    for (int ni = 0; ni < 4; ni++) {
                        float a0 = acc[mi][ni][h2 * 2];
                        float a1 = acc[mi][ni][h2 * 2 + 1];
                        s += a0 * a0 + a1 * a1;
                    }
                    s += __shfl_xor_sync(0xffffffffu, s, 1);
                    s += __shfl_xor_sync(0xffffffffu, s, 2);
                    ssum[mi][h2] = s;
                }
            if ((lane & 3) == 0) {
                int rl = warp_m * 64 + (lane >> 2);
                #pragma unroll
                for (int mi = 0; mi < 4; mi++)
                    #pragma unroll
                    for (int h2 = 0; h2 < 2; h2++)
                        red[(rl + mi * 16 + h2 * 8) * 4 + warp_n] = ssum[mi][h2];
            }
            __syncthreads();
            const float* gv = (col0 < 2048) ? gq : gk;
            float g8[4][2];
            #pragma unroll
            for (int ni = 0; ni < 4; ni++) {
                g8[ni][0] = gv[((ccol + ni * 8) & 127)];
                g8[ni][1] = gv[((ccol + ni * 8) & 127) + 1];
            }
            #pragma unroll
            for (int mi = 0; mi < 4; mi++)
                #pragma unroll
                for (int h2 = 0; h2 < 2; h2++) {
                    int rl = warp_m * 64 + (lane >> 2) + mi * 16 + h2 * 8;
                    float s = red[rl * 4 + 0] + red[rl * 4 + 1]
                            + red[rl * 4 + 2] + red[rl * 4 + 3];
                    float r = rsqrtf(s * (1.f / DH_) + 1e-6f);
                    long long o = (long long)(row0 + rl) * (2 * DIM_) + ccol;
                    #pragma unroll
                    for (int ni = 0; ni < 4; ni++) {
                        float v0 = acc[mi][ni][h2 * 2]     * r * g8[ni][0];
                        float v1 = acc[mi][ni][h2 * 2 + 1] * r * g8[ni][1];
                        *(uint32_t*)(Qh + o + ni * 8) = pack_hi2(v0, v1);
                        *(uint32_t*)(Ql + o + ni * 8) = pack_lo2(v0, v1);
                    }
                }
        } else {
            float* T = (float*)smem;
            __syncthreads();
            int lcol = warp_n * 32 + (lane & 3) * 2;
            #pragma unroll
            for (int mi = 0; mi < 4; mi++)
                #pragma unroll
                for (int h2 = 0; h2 < 2; h2++) {
                    int rl = warp_m * 64 + (lane >> 2) + mi * 16 + h2 * 8;
                    #pragma unroll
                    for (int ni = 0; ni < 4; ni++) {
                        T[rl * 129 + lcol + ni * 8]     = acc[mi][ni][h2 * 2];
                        T[rl * 129 + lcol + ni * 8 + 1] = acc[mi][ni][h2 * 2 + 1];
                    }
                }
            __syncthreads();
            int b = row0 >> 11;
            int h = (col0 - 4096) >> 7;
            int tok0g = row0 & 2047;
            long long zoff = (long long)(b * 16 + h) * DH_ * N_;
            #pragma unroll
            for (int k = 0; k < 32; k++) {
                int p = tid + k * 256;
                int d = p >> 6;
                int tk = (p & 63) * 2;
                float v0 = T[tk * 129 + d];
                float v1 = T[(tk + 1) * 129 + d];
                long long o = zoff + (long long)d * N_ + tok0g + tk;
                *(uint32_t*)(Vth + o) = pack_hi2(v0, v1);
                *(uint32_t*)(Vtl + o) = pack_lo2(v0, v1);
            }
        }
        return;
    }

    bool addc = (CaddH != nullptr);
    #pragma unroll
    for (int mi = 0; mi < 4; mi++)
        #pragma unroll
        for (int ni = 0; ni < 4; ni++) {
            long long o0 = (long long)(mrow + mi * 16) * ldc + ccol + ni * 8;
            long long o1 = o0 + 8LL * ldc;
            float2 v0 = make_float2(acc[mi][ni][0], acc[mi][ni][1]);
            float2 v1 = make_float2(acc[mi][ni][2], acc[mi][ni][3]);
            if (addc) {
                float2 h0 = unp2(*(const uint32_t*)(CaddH + o0));
                float2 l0 = unp2(*(const uint32_t*)(CaddL + o0));
                float2 h1 = unp2(*(const uint32_t*)(CaddH + o1));
                float2 l1 = unp2(*(const uint32_t*)(CaddL + o1));
                v0.x += h0.x + l0.x; v0.y += h0.y + l0.y;
                v1.x += h1.x + l1.x; v1.y += h1.y + l1.y;
            }
            *(float2*)(C + o0) = v0;
            *(float2*)(C + o1) = v1;
        }
}

// ------------- flash attention (R13-proven form) ----------------------------
#define FQ_    0
#define FKV_   32768
#define FP_    65536
#define F_RM   98304
#define F_RS   99328
#define F_M    100352
#define F_L    100608
#define FLASH_SMEM 100864

__global__ void __launch_bounds__(256, 2)
flash_attn(const __nv_bfloat16* __restrict__ qkh, const __nv_bfloat16* __restrict__ qkl,
           const __nv_bfloat16* __restrict__ vTh, const __nv_bfloat16* __restrict__ vTl,
           __nv_bfloat16* __restrict__ oh, __nv_bfloat16* __restrict__ ol) {
    extern __shared__ char smem[];
    uint32_t sb = smem_u32(smem);
    int tid = threadIdx.x, lane = tid & 31, wid = tid >> 5;
    int fm = wid >> 2, fn = wid & 3;
    int lr = lane & 15, cx = lane >> 4, swz = (lr >> 1) & 3;
    int qt = blockIdx.x, z = blockIdx.y, b = z >> 4, h = z & 15;
    long long qrow0 = (long long)b * N_ + qt * 64;
    long long krow0 = (long long)b * N_;
    int hcol = h * DH_;
    long long zoff = (long long)z * DH_ * N_;
    const float SCALE = 0.08838834764831845f;

    float* RM = (float*)(smem + F_RM);
    float* RS = (float*)(smem + F_RS);
    float* Mv = (float*)(smem + F_M);
    float* Lv = (float*)(smem + F_L);
    if (tid < 64) { Mv[tid] = -1e30f; Lv[tid] = 0.f; }

    float oacc[2][4][4];
    #pragma unroll
    for (int mi = 0; mi < 2; mi++)
        #pragma unroll
        for (int ni = 0; ni < 4; ni++)
            #pragma unroll
            for (int e = 0; e < 4; e++) oacc[mi][ni][e] = 0.f;

    {
        int rid = tid >> 2, seg = tid & 3;
        int sw = seg ^ ((rid >> 1) & 3);
        #pragma unroll
        for (int c = 0; c < 4; c++) {
            long long off = (qrow0 + rid) * (2LL * DIM_) + hcol + c * 32 + seg * 8;
            uint32_t d = sb + FQ_ + (uint32_t)(c * 8192 + rid * 64 + sw * 16);
            cp16(d, qkh + off);
            cp16(d + 4096, qkl + off);
        }
        cp_commit();
    }

    auto load_k = [&](int st, int c, int j) {
        #pragma unroll
        for (int t = 0; t < 2; t++) {
            int id = tid + t * 256, rid = id >> 2, seg = id & 3;
            int sw = seg ^ ((rid >> 1) & 3);
            long long off = (krow0 + j * 128 + rid) * (2LL * DIM_)
                          + hcol + DIM_ + c * 32 + seg * 8;
            uint32_t d = sb + FKV_ + (uint32_t)(st * 16384 + rid * 64 + sw * 16);
            cp16(d, qkh + off);
            cp16(d + 8192, qkl + off);
        }
        cp_commit();
    };
    auto load_v = [&](int st, int c, int j) {
        #pragma unroll
        for (int t = 0; t < 2; t++) {
            int id = tid + t * 256, rid = id >> 2, seg = id & 3;
            int sw = seg ^ ((rid >> 1) & 3);
            long long off = zoff + (long long)rid * N_ + j * 128 + c * 32 + seg * 8;
            uint32_t d = sb + FKV_ + (uint32_t)(st * 16384 + rid * 64 + sw * 16);
            cp16(d, vTh + off);
            cp16(d + 8192, vTl + off);
        }
        cp_commit();
    };

    int rbase = fm * 32 + (lane >> 2);
    int cq = (lane & 3) * 2;

    for (int j = 0; j < 16; j++) {
        float sacc[2][4][4];
        #pragma unroll
        for (int mi = 0; mi < 2; mi++)
            #pragma unroll
            for (int ni = 0; ni < 4; ni++)
                #pragma unroll
                for (int e = 0; e < 4; e++) sacc[mi][ni][e] = 0.f;

        load_k(0, 0, j);
        for (int c = 0; c < 4; c++) {
            cp_wait<0>();
            __syncthreads();
            if (c < 3) load_k((c + 1) & 1, c + 1, j);
            uint32_t abase = sb + FQ_ + (uint32_t)(c * 8192 + (fm * 32 + lr) * 64);
            uint32_t bbase = sb + FKV_ + (uint32_t)(((c & 1) * 16384)
                           + (fn * 32 + lr) * 64);
            #pragma unroll
            for (int s = 0; s < 2; s++) {
                uint32_t co = (uint32_t)(((s << 1) | cx) ^ swz) << 4;
                uint32_t A1[2][4], A2[2][4], Bf[4][2];
                #pragma unroll
                for (int mi = 0; mi < 2; mi++)
                    ldsm4(A1[mi][0], A1[mi][1], A1[mi][2], A1[mi][3],
                          abase + (uint32_t)(mi * 1024) + co);
                #pragma unroll
                for (int np = 0; np < 2; np++) {
                    uint32_t r0, r1, r2, r3;
                    ldsm4(r0, r1, r2, r3, bbase + (uint32_t)(np * 1024) + co);
                    Bf[2 * np][0] = r0; Bf[2 * np][1] = r2;
                    Bf[2 * np + 1][0] = r1; Bf[2 * np + 1][1] = r3;
                }
                #pragma unroll
                for (int mi = 0; mi < 2; mi++)
                    #pragma unroll
                    for (int ni = 0; ni < 4; ni++)
                        mma16816(sacc[mi][ni], A1[mi], Bf[ni]);
                #pragma unroll
                for (int mi = 0; mi < 2; mi++)
                    ldsm4(A2[mi][0], A2[mi][1], A2[mi][2], A2[mi][3],
                          abase + (uint32_t)(mi * 1024) + co + 4096);
                #pragma unroll
                for (int mi = 0; mi < 2; mi++)
                    #pragma unroll
                    for (int ni = 0; ni < 4; ni++)
                        mma16816(sacc[mi][ni], A2[mi], Bf[ni]);
                #pragma unroll
                for (int np = 0; np < 2; np++) {
                    uint32_t r0, r1, r2, r3;
                    ldsm4(r0, r1, r2, r3, bbase + (uint32_t)(np * 1024) + co + 8192);
                    Bf[2 * np][0] = r0; Bf[2 * np][1] = r2;
                    Bf[2 * np + 1][0] = r1; Bf[2 * np + 1][1] = r3;
                }
                #pragma unroll
                for (int mi = 0; mi < 2; mi++)
                    #pragma unroll
                    for (int ni = 0; ni < 4; ni++)
                        mma16816(sacc[mi][ni], A1[mi], Bf[ni]);
            }
        }

        float rmax[2][2];
        #pragma unroll
        for (int mi = 0; mi < 2; mi++)
            #pragma unroll
            for (int h2 = 0; h2 < 2; h2++) {
                float m = -1e30f;
                #pragma unroll
                for (int ni = 0; ni < 4; ni++) {
                    sacc[mi][ni][h2 * 2]     *= SCALE;
                    sacc[mi][ni][h2 * 2 + 1] *= SCALE;
                    m = fmaxf(m, fmaxf(sacc[mi][ni][h2 * 2], sacc[mi][ni][h2 * 2 + 1]));
                }
                #pragma unroll
                for (int o = 1; o <= 2; o <<= 1)
                    m = fmaxf(m, __shfl_xor_sync(0xffffffffu, m, o));
                rmax[mi][h2] = m;
            }
        if ((lane & 3) == 0)
            #pragma unroll
            for (int mi = 0; mi < 2; mi++)
                #pragma unroll
                for (int h2 = 0; h2 < 2; h2++)
                    RM[(rbase + mi * 16 + h2 * 8) * 4 + fn] = rmax[mi][h2];
        __syncthreads();

        load_v(0, 0, j);

        float mnew[2][2], fact[2][2], rsum[2][2];
        #pragma unroll
        for (int mi = 0; mi < 2; mi++)
            #pragma unroll
            for (int h2 = 0; h2 < 2; h2++) {
                int r = rbase + mi * 16 + h2 * 8;
                float bm = fmaxf(fmaxf(RM[r * 4 + 0], RM[r * 4 + 1]),
                                 fmaxf(RM[r * 4 + 2], RM[r * 4 + 3]));
                float mo = Mv[r];
                float mn = fmaxf(mo, bm);
                mnew[mi][h2] = mn;
                fact[mi][h2] = __expf(mo - mn);
                rsum[mi][h2] = 0.f;
            }
        #pragma unroll
        for (int mi = 0; mi < 2; mi++)
            #pragma unroll
            for (int ni = 0; ni < 4; ni++)
                #pragma unroll
                for (int e = 0; e < 4; e++) {
                    int h2 = e >> 1;
                    oacc[mi][ni][e] *= fact[mi][h2];
                    float p = __expf(sacc[mi][ni][e] - mnew[mi][h2]);
                    sacc[mi][ni][e] = p;
                    rsum[mi][h2] += p;
                }
        #pragma unroll
        for (int o = 1; o <= 2; o <<= 1)
            #pragma unroll
            for (int mi = 0; mi < 2; mi++)
                #pragma unroll
                for (int h2 = 0; h2 < 2; h2++)
                    rsum[mi][h2] += __shfl_xor_sync(0xffffffffu, rsum[mi][h2], o);
        if ((lane & 3) == 0)
            #pragma unroll
            for (int mi = 0; mi < 2; mi++)
                #pragma unroll
                for (int h2 = 0; h2 < 2; h2++)
                    RS[(rbase + mi * 16 + h2 * 8) * 4 + fn] = rsum[mi][h2];
        #pragma unroll
        for (int mi = 0; mi < 2; mi++)
            #pragma unroll
            for (int h2 = 0; h2 < 2; h2++) {
                int rl = rbase + mi * 16 + h2 * 8;
                int key = (rl >> 1) & 3;
                uint32_t rowb = sb + FP_ + (uint32_t)(fn * 4096) + (uint32_t)(rl * 64);
                #pragma unroll
                for (int ni = 0; ni < 4; ni++) {
                    int cc = cq + ni * 8;
                    uint32_t boff = rowb
                        + (uint32_t)((((cc >> 3) ^ key) << 4) + (cc & 7) * 2);
                    float p0 = sacc[mi][ni][h2 * 2];
                    float p1 = sacc[mi][ni][h2 * 2 + 1];
                    st32(boff,         pack_hi2(p0, p1));
                    st32(boff + 16384, pack_lo2(p0, p1));
                }
            }
        __syncthreads();
        if (fn == 0 && (lane & 3) == 0)
            #pragma unroll
            for (int mi = 0; mi < 2; mi++)
                #pragma unroll
                for (int h2 = 0; h2 < 2; h2++) {
                    int r = rbase + mi * 16 + h2 * 8;
                    Mv[r] = mnew[mi][h2];
                    Lv[r] = Lv[r] * fact[mi][h2]
                          + RS[r * 4] + RS[r * 4 + 1] + RS[r * 4 + 2] + RS[r * 4 + 3];
                }

        for (int c = 0; c < 4; c++) {
            cp_wait<0>();
            __syncthreads();
            if (c < 3) load_v((c + 1) & 1, c + 1, j);
            uint32_t pbase = sb + FP_ + (uint32_t)(c * 4096)
                           + (uint32_t)((fm * 32 + lr) * 64);
            uint32_t vbase = sb + FKV_ + (uint32_t)(((c & 1) * 16384)
                           + (fn * 32 + lr) * 64);
            #pragma unroll
            for (int s = 0; s < 2; s++) {
                uint32_t co = (uint32_t)(((s << 1) | cx) ^ swz) << 4;
                uint32_t A1[2][4], A2[2][4], Bf[4][2];
                #pragma unroll
                for (int mi = 0; mi < 2; mi++)
                    ldsm4(A1[mi][0], A1[mi][1], A1[mi][2], A1[mi][3],
                          pbase + (uint32_t)(mi * 1024) + co);
                #pragma unroll
                for (int np = 0; np < 2; np++) {
                    uint32_t r0, r1, r2, r3;
                    ldsm4(r0, r1, r2, r3, vbase + (uint32_t)(np * 1024) + co);
                    Bf[2 * np][0] = r0; Bf[2 * np][1] = r2;
                    Bf[2 * np + 1][0] = r1; Bf[2 * np + 1][1] = r3;
                }
                #pragma unroll
                for (int mi = 0; mi < 2; mi++)
                    #pragma unroll
                    for (int ni = 0; ni < 4; ni++)
                        mma16816(oacc[mi][ni], A1[mi], Bf[ni]);
                #pragma unroll
                for (int mi = 0; mi < 2; mi++)
                    ldsm4(A2[mi][0], A2[mi][1], A2[mi][2], A2[mi][3],
                          pbase + (uint32_t)(mi * 1024) + co + 16384);
                #pragma unroll
                for (int mi = 0; mi < 2; mi++)
                    #pragma unroll
                    for (int ni = 0; ni < 4; ni++)
                        mma16816(oacc[mi][ni], A2[mi], Bf[ni]);
                #pragma unroll
                for (int np = 0; np < 2; np++) {
                    uint32_t r0, r1, r2, r3;
                    ldsm4(r0, r1, r2, r3, vbase + (uint32_t)(np * 1024) + co + 8192);
                    Bf[2 * np][0] = r0; Bf[2 * np][1] = r2;
                    Bf[2 * np + 1][0] = r1; Bf[2 * np + 1][1] = r3;
                }
                #pragma unroll
                for (int mi = 0; mi < 2; mi++)
                    #pragma unroll
                    for (int ni = 0; ni < 4; ni++)
                        mma16816(oacc[mi][ni], A1[mi], Bf[ni]);
            }
        }
        __syncthreads();
    }

    #pragma unroll
    for (int mi = 0; mi < 2; mi++)
        #pragma unroll
        for (int h2 = 0; h2 < 2; h2++) {
            int rl = rbase + mi * 16 + h2 * 8;
            float li = 1.f / Lv[rl];
            long long row = (qrow0 + rl) * (long long)DIM_ + hcol + fn * 32;
            #pragma unroll
            for (int ni = 0; ni < 4; ni++) {
                float v0 = oacc[mi][ni][h2 * 2] * li;
                float v1 = oacc[mi][ni][h2 * 2 + 1] * li;
                long long o = row + cq + ni * 8;
                *(uint32_t*)(oh + o) = pack_hi2(v0, v1);
                *(uint32_t*)(ol + o) = pack_lo2(v0, v1);
            }
        }
}

// ---------------------------------------------------------------------------
extern "C" void kernel_launch(void* const* d_in, const int* in_sizes, int n_in,
                              void* d_out, int out_size) {
    const float* x      = (const float*)d_in[0];
    const float* emb    = (const float*)d_in[1];
    const float* W_emb  = (const float*)d_in[2];
    const float* b_emb  = (const float*)d_in[3];
    const float* g_norm = (const float*)d_in[4];
    const float* W_qkv  = (const float*)d_in[5];
    const float* g_q    = (const float*)d_in[6];
    const float* g_k    = (const float*)d_in[7];
    const float* W_out  = (const float*)d_in[8];
    float* out = (float*)d_out;
    (void)in_sizes; (void)n_in; (void)out_size;

    float *ss;
    __nv_bfloat16 *xnh, *xnl, *wqTh, *wqTl, *woTh, *woTl;
    __nv_bfloat16 *qkh, *qkl, *vTh, *vTl, *oh, *ol;
    cudaGetSymbolAddress((void**)&ss,   g_ss);
    cudaGetSymbolAddress((void**)&xnh,  g_xnh);
    cudaGetSymbolAddress((void**)&xnl,  g_xnl);
    cudaGetSymbolAddress((void**)&wqTh, g_wqTh);
    cudaGetSymbolAddress((void**)&wqTl, g_wqTl);
    cudaGetSymbolAddress((void**)&woTh, g_woTh);
    cudaGetSymbolAddress((void**)&woTl, g_woTl);
    cudaGetSymbolAddress((void**)&qkh,  g_qkh);
    cudaGetSymbolAddress((void**)&qkl,  g_qkl);
    cudaGetSymbolAddress((void**)&vTh,  g_vTh);
    cudaGetSymbolAddress((void**)&vTl,  g_vTl);
    cudaGetSymbolAddress((void**)&oh,   g_oh);
    cudaGetSymbolAddress((void**)&ol,   g_ol);

    cudaFuncSetAttribute(gemm_bf16x3,
                         cudaFuncAttributeMaxDynamicSharedMemorySize, GEMM_SMEM);
    cudaFuncSetAttribute(flash_attn,
                         cudaFuncAttributeMaxDynamicSharedMemorySize, FLASH_SMEM);

    // One-time side-stream + events (created on the uncaptured correctness
    // call; only record/wait edges appear inside graph capture).
    static cudaStream_t s2 = nullptr;
    static cudaEvent_t evFork = nullptr, evJoin = nullptr;
    if (s2 == nullptr) {
        cudaStreamCreateWithFlags(&s2, cudaStreamNonBlocking);
        cudaEventCreateWithFlags(&evFork, cudaEventDisableTiming);
        cudaEventCreateWithFlags(&evJoin, cudaEventDisableTiming);
    }

    // fork: weight transposes run concurrently with scale_shift + xnorm
    cudaEventRecord(evFork, 0);
    cudaStreamWaitEvent(s2, evFork, 0);
    k_tsplit<<<dim3(QKVC_ / 32, DIM_ / 32), dim3(32, 8), 0, s2>>>(
        W_qkv, DIM_, QKVC_, wqTh, wqTl);
    k_tsplit<<<dim3(DIM_ / 32, DIM_ / 32), dim3(32, 8), 0, s2>>>(
        W_out, DIM_, DIM_, woTh, woTl);
    cudaEventRecord(evJoin, s2);

    k_scale_shift<<<dim3((2 * DIM_) / 256, B_), 256>>>(emb, W_emb, b_emb, ss);
    k_xnorm<<<TOK_, 256>>>(x, g_norm, ss, xnh, xnl);

    cudaStreamWaitEvent(0, evJoin, 0);   // join before the QKV GEMM

    gemm_bf16x3<<<dim3(QKVC_ / 128, TOK_ / 128, 1), 256, GEMM_SMEM>>>(
        xnh, xnl, DIM_, wqTh, wqTl, DIM_, nullptr, nullptr, nullptr, 0, DIM_,
        g_q, g_k, qkh, qkl, vTh, vTl);
    flash_attn<<<dim3(N_ / 64, BH_), 256, FLASH_SMEM>>>(
        qkh, qkl, vTh, vTl, oh, ol);
    gemm_bf16x3<<<dim3(DIM_ / 128, TOK_ / 128, 1), 256, GEMM_SMEM>>>(
        oh, ol, DIM_, woTh, woTl, DIM_, oh, ol, out, DIM_, DIM_,
        nullptr, nullptr, nullptr, nullptr, nullptr, nullptr);
}

// round 17
// speedup vs baseline: 1.0401x; 1.0327x over previous
#include <cuda_runtime.h>
#include <cuda_bf16.h>
#include <cstdint>

#define B_     4
#define N_     2048
#define DIM_   2048
#define H_     16
#define DH_    128
#define TOK_   (B_ * N_)
#define QKVC_  (3 * DIM_)
#define BH_    (B_ * H_)
#define SK_    8

__device__ float          g_ss[B_ * 2 * DIM_];
__device__ float          g_ssp[SK_ * B_ * 2 * DIM_];
__device__ __nv_bfloat16  g_xnh[(long long)TOK_ * DIM_];
__device__ __nv_bfloat16  g_xnl[(long long)TOK_ * DIM_];
__device__ __nv_bfloat16  g_wqTh[(long long)QKVC_ * DIM_];
__device__ __nv_bfloat16  g_wqTl[(long long)QKVC_ * DIM_];
__device__ __nv_bfloat16  g_woTh[(long long)DIM_ * DIM_];
__device__ __nv_bfloat16  g_woTl[(long long)DIM_ * DIM_];
__device__ __nv_bfloat16  g_qkh[(long long)TOK_ * 2 * DIM_];
__device__ __nv_bfloat16  g_qkl[(long long)TOK_ * 2 * DIM_];
__device__ __nv_bfloat16  g_vTh[(long long)BH_ * DH_ * N_];
__device__ __nv_bfloat16  g_vTl[(long long)BH_ * DH_ * N_];
__device__ __nv_bfloat16  g_oh[(long long)TOK_ * DIM_];
__device__ __nv_bfloat16  g_ol[(long long)TOK_ * DIM_];

__device__ __forceinline__ uint32_t smem_u32(const void* p) {
    uint32_t a;
    asm("{ .reg .u64 t; cvta.to.shared.u64 t, %1; cvt.u32.u64 %0, t; }"
        : "=r"(a) : "l"(p));
    return a;
}
__device__ __forceinline__ void cp16(uint32_t dst, const void* src) {
    asm volatile("cp.async.cg.shared.global [%0], [%1], 16;"
                 :: "r"(dst), "l"(__cvta_generic_to_global(src)));
}
__device__ __forceinline__ void cp_commit() {
    asm volatile("cp.async.commit_group;" ::: "memory");
}
template <int NN>
__device__ __forceinline__ void cp_wait() {
    asm volatile("cp.async.wait_group %0;" :: "n"(NN) : "memory");
}
__device__ __forceinline__ void ldsm4(uint32_t& r0, uint32_t& r1,
                                      uint32_t& r2, uint32_t& r3, uint32_t a) {
    asm volatile("ldmatrix.sync.aligned.m8n8.x4.shared.b16 {%0,%1,%2,%3}, [%4];"
                 : "=r"(r0), "=r"(r1), "=r"(r2), "=r"(r3) : "r"(a));
}
__device__ __forceinline__ void mma16816(float* d, const uint32_t* a,
                                         const uint32_t* b) {
    asm volatile(
        "mma.sync.aligned.m16n8k16.row.col.f32.bf16.bf16.f32 "
        "{%0,%1,%2,%3}, {%4,%5,%6,%7}, {%8,%9}, {%0,%1,%2,%3};"
        : "+f"(d[0]), "+f"(d[1]), "+f"(d[2]), "+f"(d[3])
        : "r"(a[0]), "r"(a[1]), "r"(a[2]), "r"(a[3]), "r"(b[0]), "r"(b[1]));
}
__device__ __forceinline__ void st32(uint32_t a, uint32_t v) {
    asm volatile("st.shared.b32 [%0], %1;" :: "r"(a), "r"(v) : "memory");
}
__device__ __forceinline__ void split_store4(float4 v,
                                             __nv_bfloat16* __restrict__ hi,
                                             __nv_bfloat16* __restrict__ lo) {
    __nv_bfloat16 h[4], l[4];
    float f[4] = {v.x, v.y, v.z, v.w};
    #pragma unroll
    for (int i = 0; i < 4; i++) {
        h[i] = __float2bfloat16(f[i]);
        l[i] = __float2bfloat16(f[i] - __bfloat162float(h[i]));
    }
    *(uint2*)hi = *(const uint2*)h;
    *(uint2*)lo = *(const uint2*)l;
}
__device__ __forceinline__ uint32_t pack_hi2(float a, float b) {
    __nv_bfloat16 h[2] = {__float2bfloat16(a), __float2bfloat16(b)};
    return *(const uint32_t*)h;
}
__device__ __forceinline__ uint32_t pack_lo2(float a, float b) {
    __nv_bfloat16 ha = __float2bfloat16(a), hb = __float2bfloat16(b);
    __nv_bfloat16 l[2] = {__float2bfloat16(a - __bfloat162float(ha)),
                          __float2bfloat16(b - __bfloat162float(hb))};
    return *(const uint32_t*)l;
}
__device__ __forceinline__ float2 unp2(uint32_t u) {
    __nv_bfloat16* p = (__nv_bfloat16*)&u;
    return make_float2(__bfloat162float(p[0]), __bfloat162float(p[1]));
}
__device__ __forceinline__ float blk_sum256(float v) {
    __shared__ float red[8];
    __shared__ float tot;
    #pragma unroll
    for (int o = 16; o > 0; o >>= 1) v += __shfl_xor_sync(0xffffffffu, v, o);
    if ((threadIdx.x & 31) == 0) red[threadIdx.x >> 5] = v;
    __syncthreads();
    if (threadIdx.x == 0) {
        float s = 0.f;
        #pragma unroll
        for (int i = 0; i < 8; i++) s += red[i];
        tot = s;
    }
    __syncthreads();
    return tot;
}

// ---- scale_shift: split-K partials (deterministic, no atomics) -------------
__global__ void k_ss_part(const float* __restrict__ emb,
                          const float* __restrict__ W,
                          float* __restrict__ ssp) {
    int c = blockIdx.x * 256 + threadIdx.x;     // 0..4095
    int b = blockIdx.y;
    int sk = blockIdx.z;                        // 0..SK_-1
    const float* e = emb + b * DIM_ + sk * (DIM_ / SK_);
    const float* wp = W + (long long)(sk * (DIM_ / SK_)) * (2 * DIM_) + c;
    float acc = 0.f;
    #pragma unroll 8
    for (int k = 0; k < DIM_ / SK_; k++)
        acc = fmaf(e[k], wp[(long long)k * (2 * DIM_)], acc);
    ssp[((long long)sk * B_ + b) * (2 * DIM_) + c] = acc;
}
__global__ void k_ss_reduce(const float* __restrict__ ssp,
                            const float* __restrict__ bias,
                            float* __restrict__ ss) {
    int c = blockIdx.x * 256 + threadIdx.x;
    int b = blockIdx.y;
    float acc = bias[c];
    #pragma unroll
    for (int sk = 0; sk < SK_; sk++)
        acc += ssp[((long long)sk * B_ + b) * (2 * DIM_) + c];
    ss[b * (2 * DIM_) + c] = acc;
}

__global__ void k_xnorm(const float* __restrict__ x,
                        const float* __restrict__ g,
                        const float* __restrict__ ss,
                        __nv_bfloat16* __restrict__ xh,
                        __nv_bfloat16* __restrict__ xl) {
    long long row = blockIdx.x;
    int b = (int)(row >> 11);
    const float4* xr = (const float4*)(x + row * DIM_);
    float4 v0 = xr[threadIdx.x];
    float4 v1 = xr[threadIdx.x + 256];
    float s = v0.x * v0.x + v0.y * v0.y + v0.z * v0.z + v0.w * v0.w
            + v1.x * v1.x + v1.y * v1.y + v1.z * v1.z + v1.w * v1.w;
    s = blk_sum256(s);
    float r = rsqrtf(s * (1.f / DIM_) + 1e-6f);
    const float* sc = ss + b * (2 * DIM_);
    const float* sh = sc + DIM_;
    int c0 = threadIdx.x * 4, c1 = (threadIdx.x + 256) * 4;
    float4 o0, o1;
    o0.x = fmaf(v0.x * r * g[c0 + 0], 1.f + sc[c0 + 0], sh[c0 + 0]);
    o0.y = fmaf(v0.y * r * g[c0 + 1], 1.f + sc[c0 + 1], sh[c0 + 1]);
    o0.z = fmaf(v0.z * r * g[c0 + 2], 1.f + sc[c0 + 2], sh[c0 + 2]);
    o0.w = fmaf(v0.w * r * g[c0 + 3], 1.f + sc[c0 + 3], sh[c0 + 3]);
    o1.x = fmaf(v1.x * r * g[c1 + 0], 1.f + sc[c1 + 0], sh[c1 + 0]);
    o1.y = fmaf(v1.y * r * g[c1 + 1], 1.f + sc[c1 + 1], sh[c1 + 1]);
    o1.z = fmaf(v1.z * r * g[c1 + 2], 1.f + sc[c1 + 2], sh[c1 + 2]);
    o1.w = fmaf(v1.w * r * g[c1 + 3], 1.f + sc[c1 + 3], sh[c1 + 3]);
    long long base = row * DIM_;
    split_store4(o0, xh + base + c0, xl + base + c0);
    split_store4(o1, xh + base + c1, xl + base + c1);
}

__global__ void k_tsplit(const float* __restrict__ W, int KR, int NC,
                         __nv_bfloat16* __restrict__ Th,
                         __nv_bfloat16* __restrict__ Tl) {
    __shared__ float t[32][33];
    int c0 = blockIdx.x * 32, r0 = blockIdx.y * 32;
    for (int i = threadIdx.y; i < 32; i += 8)
        t[i][threadIdx.x] = W[(long long)(r0 + i) * NC + c0 + threadIdx.x];
    __syncthreads();
    for (int i = threadIdx.y; i < 32; i += 8) {
        float v = t[threadIdx.x][i];
        long long o = (long long)(c0 + i) * KR + r0 + threadIdx.x;
        __nv_bfloat16 h = __float2bfloat16(v);
        Th[o] = h;
        Tl[o] = __float2bfloat16(v - __bfloat162float(h));
    }
}

// ------------- generic GEMM + fused epilogues -------------------------------
#define CHUNK  32
#define ROWB   64
#define TILEB  (128 * ROWB)
#define STAGEB (4 * TILEB)
#define NSTAGE 3
#define GEMM_SMEM (NSTAGE * STAGEB)

__global__ void __launch_bounds__(256, 2)
gemm_bf16x3(const __nv_bfloat16* __restrict__ Ahi, const __nv_bfloat16* __restrict__ Alo,
            int lda,
            const __nv_bfloat16* __restrict__ Bhi, const __nv_bfloat16* __restrict__ Blo,
            int ldb,
            const __nv_bfloat16* __restrict__ CaddH, const __nv_bfloat16* __restrict__ CaddL,
            float* __restrict__ C, int ldc, int K,
            const float* __restrict__ gq, const float* __restrict__ gk,
            __nv_bfloat16* __restrict__ Qh, __nv_bfloat16* __restrict__ Ql,
            __nv_bfloat16* __restrict__ Vth, __nv_bfloat16* __restrict__ Vtl) {
    extern __shared__ char smem[];
    uint32_t sb = smem_u32(smem);
    int tid = threadIdx.x, wid = tid >> 5, lane = tid & 31;
    int warp_m = wid >> 2, warp_n = wid & 3;
    int row0 = blockIdx.y * 128, col0 = blockIdx.x * 128;

    float acc[4][4][4];
    #pragma unroll
    for (int i = 0; i < 4; i++)
        #pragma unroll
        for (int j = 0; j < 4; j++)
            #pragma unroll
            for (int r = 0; r < 4; r++) acc[i][j][r] = 0.f;

    int NC = K / CHUNK;

    // --- hoisted load-path invariants (R16) --------------------------------
    int rid0 = tid >> 2, seg = tid & 3;
    int sw0 = seg ^ ((rid0 >> 1) & 3);          // sw invariant under rid+64
    uint32_t dst0 = (uint32_t)(rid0 * ROWB + sw0 * 16);
    uint32_t dst1 = dst0 + 64u * ROWB;
    const __nv_bfloat16* pAh = Ahi + (long long)(row0 + rid0) * lda + seg * 8;
    const __nv_bfloat16* pAl = Alo + (long long)(row0 + rid0) * lda + seg * 8;
    const __nv_bfloat16* pBh = Bhi + (long long)(col0 + rid0) * ldb + seg * 8;
    const __nv_bfloat16* pBl = Blo + (long long)(col0 + rid0) * ldb + seg * 8;
    long long offA = 64LL * lda, offB = 64LL * ldb;

    auto load_stage = [&](int slot, int k0) {
        uint32_t base = sb + slot * STAGEB;
        cp16(base + dst0,                 pAh + k0);
        cp16(base + dst1,                 pAh + offA + k0);
        cp16(base + TILEB + dst0,         pAl + k0);
        cp16(base + TILEB + dst1,         pAl + offA + k0);
        cp16(base + 2 * TILEB + dst0,     pBh + k0);
        cp16(base + 2 * TILEB + dst1,     pBh + offB + k0);
        cp16(base + 3 * TILEB + dst0,     pBl + k0);
        cp16(base + 3 * TILEB + dst1,     pBl + offB + k0);
        cp_commit();
    };
    load_stage(0, 0);
    load_stage(1, CHUNK);

    int lr = lane & 15, cx = lane >> 4, swz = (lr >> 1) & 3;
    for (int i = 0; i < NC; i++) {
        if (i < NC - 1) cp_wait<1>(); else cp_wait<0>();
        __syncthreads();
        if (i + 2 < NC) load_stage((i + 2) % NSTAGE, (i + 2) * CHUNK);
        int slot = i % NSTAGE;
        uint32_t abase = sb + slot * STAGEB + (uint32_t)((warp_m * 64 + lr) * ROWB);
        uint32_t bbase = sb + slot * STAGEB + 2 * TILEB
                       + (uint32_t)((warp_n * 32 + lr) * ROWB);
        #pragma unroll
        for (int s = 0; s < 2; s++) {
            uint32_t co = (uint32_t)(((s << 1) | cx) ^ swz) << 4;
            uint32_t A1[4][4], A2[4][4], Bf[4][2];
            #pragma unroll
            for (int mi = 0; mi < 4; mi++)
                ldsm4(A1[mi][0], A1[mi][1], A1[mi][2], A1[mi][3],
                      abase + (uint32_t)(mi * 16 * ROWB) + co);
            #pragma unroll
            for (int np = 0; np < 2; np++) {
                uint32_t r0, r1, r2, r3;
                ldsm4(r0, r1, r2, r3, bbase + (uint32_t)(np * 16 * ROWB) + co);
                Bf[2 * np][0] = r0; Bf[2 * np][1] = r2;
                Bf[2 * np + 1][0] = r1; Bf[2 * np + 1][1] = r3;
            }
            #pragma unroll
            for (int mi = 0; mi < 4; mi++)
                #pragma unroll
                for (int ni = 0; ni < 4; ni++)
                    mma16816(acc[mi][ni], A1[mi], Bf[ni]);
            #pragma unroll
            for (int mi = 0; mi < 4; mi++)
                ldsm4(A2[mi][0], A2[mi][1], A2[mi][2], A2[mi][3],
                      abase + (uint32_t)(mi * 16 * ROWB) + co + TILEB);
            #pragma unroll
            for (int mi = 0; mi < 4; mi++)
                #pragma unroll
                for (int ni = 0; ni < 4; ni++)
                    mma16816(acc[mi][ni], A2[mi], Bf[ni]);
            #pragma unroll
            for (int np = 0; np < 2; np++) {
                uint32_t r0, r1, r2, r3;
                ldsm4(r0, r1, r2, r3,
                      bbase + (uint32_t)(np * 16 * ROWB) + co + TILEB);
                Bf[2 * np][0] = r0; Bf[2 * np][1] = r2;
                Bf[2 * np + 1][0] = r1; Bf[2 * np + 1][1] = r3;
            }
            #pragma unroll
            for (int mi = 0; mi < 4; mi++)
                #pragma unroll
                for (int ni = 0; ni < 4; ni++)
                    mma16816(acc[mi][ni], A1[mi], Bf[ni]);
        }
    }

    int mrow = row0 + warp_m * 64 + (lane >> 2);
    int ccol = col0 + warp_n * 32 + (lane & 3) * 2;

    if (Qh != nullptr) {
        if (col0 < 4096) {
            float* red = (float*)smem;
            __syncthreads();
            float ssum[4][2];
            #pragma unroll
            for (int mi = 0; mi < 4; mi++)
                #pragma unroll
                for (int h2 = 0; h2 < 2; h2++) {
                    float s = 0.f;
                    #pragma unroll
                    for (int ni = 0; ni < 4; ni++) {
                        float a0 = acc[mi][ni][h2 * 2];
                        float a1 = acc[mi][ni][h2 * 2 + 1];
                        s += a0 * a0 + a1 * a1;
                    }
                    s += __shfl_xor_sync(0xffffffffu, s, 1);
                    s += __shfl_xor_sync(0xffffffffu, s, 2);
                    ssum[mi][h2] = s;
                }
            if ((lane & 3) == 0) {
                int rl = warp_m * 64 + (lane >> 2);
                #pragma unroll
                for (int mi = 0; mi < 4; mi++)
                    #pragma unroll
                    for (int h2 = 0; h2 < 2; h2++)
                        red[(rl + mi * 16 + h2 * 8) * 4 + warp_n] = ssum[mi][h2];
            }
            __syncthreads();
            // fold attention scale 1/sqrt(dh) into the q gains
            float scl = (col0 < 2048) ? 0.08838834764831845f : 1.0f;
            const float* gv = (col0 < 2048) ? gq : gk;
            float g8[4][2];
            #pragma unroll
            for (int ni = 0; ni < 4; ni++) {
                g8[ni][0] = gv[((ccol + ni * 8) & 127)] * scl;
                g8[ni][1] = gv[((ccol + ni * 8) & 127) + 1] * scl;
            }
            #pragma unroll
            for (int mi = 0; mi < 4; mi++)
                #pragma unroll
                for (int h2 = 0; h2 < 2; h2++) {
                    int rl = warp_m * 64 + (lane >> 2) + mi * 16 + h2 * 8;
                    float s = red[rl * 4 + 0] + red[rl * 4 + 1]
                            + red[rl * 4 + 2] + red[rl * 4 + 3];
                    float r = rsqrtf(s * (1.f / DH_) + 1e-6f);
                    long long o = (long long)(row0 + rl) * (2 * DIM_) + ccol;
                    #pragma unroll
                    for (int ni = 0; ni < 4; ni++) {
                        float v0 = acc[mi][ni][h2 * 2]     * r * g8[ni][0];
                        float v1 = acc[mi][ni][h2 * 2 + 1] * r * g8[ni][1];
                        *(uint32_t*)(Qh + o + ni * 8) = pack_hi2(v0, v1);
                        *(uint32_t*)(Ql + o + ni * 8) = pack_lo2(v0, v1);
                    }
                }
        } else {
            float* T = (float*)smem;
            __syncthreads();
            int lcol = warp_n * 32 + (lane & 3) * 2;
            #pragma unroll
            for (int mi = 0; mi < 4; mi++)
                #pragma unroll
                for (int h2 = 0; h2 < 2; h2++) {
                    int rl = warp_m * 64 + (lane >> 2) + mi * 16 + h2 * 8;
                    #pragma unroll
                    for (int ni = 0; ni < 4; ni++) {
                        T[rl * 129 + lcol + ni * 8]     = acc[mi][ni][h2 * 2];
                        T[rl * 129 + lcol + ni * 8 + 1] = acc[mi][ni][h2 * 2 + 1];
                    }
                }
            __syncthreads();
            int b = row0 >> 11;
            int h = (col0 - 4096) >> 7;
            int tok0g = row0 & 2047;
            long long zoff = (long long)(b * 16 + h) * DH_ * N_;
            #pragma unroll
            for (int k = 0; k < 32; k++) {
                int p = tid + k * 256;
                int d = p >> 6;
                int tk = (p & 63) * 2;
                float v0 = T[tk * 129 + d];
                float v1 = T[(tk + 1) * 129 + d];
                long long o = zoff + (long long)d * N_ + tok0g + tk;
                *(uint32_t*)(Vth + o) = pack_hi2(v0, v1);
                *(uint32_t*)(Vtl + o) = pack_lo2(v0, v1);
            }
        }
        return;
    }

    bool addc = (CaddH != nullptr);
    #pragma unroll
    for (int mi = 0; mi < 4; mi++)
        #pragma unroll
        for (int ni = 0; ni < 4; ni++) {
            long long o0 = (long long)(mrow + mi * 16) * ldc + ccol + ni * 8;
            long long o1 = o0 + 8LL * ldc;
            float2 v0 = make_float2(acc[mi][ni][0], acc[mi][ni][1]);
            float2 v1 = make_float2(acc[mi][ni][2], acc[mi][ni][3]);
            if (addc) {
                float2 h0 = unp2(*(const uint32_t*)(CaddH + o0));
                float2 l0 = unp2(*(const uint32_t*)(CaddL + o0));
                float2 h1 = unp2(*(const uint32_t*)(CaddH + o1));
                float2 l1 = unp2(*(const uint32_t*)(CaddL + o1));
                v0.x += h0.x + l0.x; v0.y += h0.y + l0.y;
                v1.x += h1.x + l1.x; v1.y += h1.y + l1.y;
            }
            *(float2*)(C + o0) = v0;
            *(float2*)(C + o1) = v1;
        }
}

// ------------- flash attention (R13-proven; SCALE pre-folded into q) --------
#define FQ_    0
#define FKV_   32768
#define FP_    65536
#define F_RM   98304
#define F_RS   99328
#define F_M    100352
#define F_L    100608
#define FLASH_SMEM 100864

__global__ void __launch_bounds__(256, 2)
flash_attn(const __nv_bfloat16* __restrict__ qkh, const __nv_bfloat16* __restrict__ qkl,
           const __nv_bfloat16* __restrict__ vTh, const __nv_bfloat16* __restrict__ vTl,
           __nv_bfloat16* __restrict__ oh, __nv_bfloat16* __restrict__ ol) {
    extern __shared__ char smem[];
    uint32_t sb = smem_u32(smem);
    int tid = threadIdx.x, lane = tid & 31, wid = tid >> 5;
    int fm = wid >> 2, fn = wid & 3;
    int lr = lane & 15, cx = lane >> 4, swz = (lr >> 1) & 3;
    int qt = blockIdx.x, z = blockIdx.y, b = z >> 4, h = z & 15;
    long long qrow0 = (long long)b * N_ + qt * 64;
    long long krow0 = (long long)b * N_;
    int hcol = h * DH_;
    long long zoff = (long long)z * DH_ * N_;

    float* RM = (float*)(smem + F_RM);
    float* RS = (float*)(smem + F_RS);
    float* Mv = (float*)(smem + F_M);
    float* Lv = (float*)(smem + F_L);
    if (tid < 64) { Mv[tid] = -1e30f; Lv[tid] = 0.f; }

    float oacc[2][4][4];
    #pragma unroll
    for (int mi = 0; mi < 2; mi++)
        #pragma unroll
        for (int ni = 0; ni < 4; ni++)
            #pragma unroll
            for (int e = 0; e < 4; e++) oacc[mi][ni][e] = 0.f;

    {
        int rid = tid >> 2, seg = tid & 3;
        int sw = seg ^ ((rid >> 1) & 3);
        #pragma unroll
        for (int c = 0; c < 4; c++) {
            long long off = (qrow0 + rid) * (2LL * DIM_) + hcol + c * 32 + seg * 8;
            uint32_t d = sb + FQ_ + (uint32_t)(c * 8192 + rid * 64 + sw * 16);
            cp16(d, qkh + off);
            cp16(d + 4096, qkl + off);
        }
        cp_commit();
    }

    auto load_k = [&](int st, int c, int j) {
        #pragma unroll
        for (int t = 0; t < 2; t++) {
            int id = tid + t * 256, rid = id >> 2, seg = id & 3;
            int sw = seg ^ ((rid >> 1) & 3);
            long long off = (krow0 + j * 128 + rid) * (2LL * DIM_)
                          + hcol + DIM_ + c * 32 + seg * 8;
            uint32_t d = sb + FKV_ + (uint32_t)(st * 16384 + rid * 64 + sw * 16);
            cp16(d, qkh + off);
            cp16(d + 8192, qkl + off);
        }
        cp_commit();
    };
    auto load_v = [&](int st, int c, int j) {
        #pragma unroll
        for (int t = 0; t < 2; t++) {
            int id = tid + t * 256, rid = id >> 2, seg = id & 3;
            int sw = seg ^ ((rid >> 1) & 3);
            long long off = zoff + (long long)rid * N_ + j * 128 + c * 32 + seg * 8;
            uint32_t d = sb + FKV_ + (uint32_t)(st * 16384 + rid * 64 + sw * 16);
            cp16(d, vTh + off);
            cp16(d + 8192, vTl + off);
        }
        cp_commit();
    };

    int rbase = fm * 32 + (lane >> 2);
    int cq = (lane & 3) * 2;

    for (int j = 0; j < 16; j++) {
        float sacc[2][4][4];
        #pragma unroll
        for (int mi = 0; mi < 2; mi++)
            #pragma unroll
            for (int ni = 0; ni < 4; ni++)
                #pragma unroll
                for (int e = 0; e < 4; e++) sacc[mi][ni][e] = 0.f;

        load_k(0, 0, j);
        for (int c = 0; c < 4; c++) {
            cp_wait<0>();
            __syncthreads();
            if (c < 3) load_k((c + 1) & 1, c + 1, j);
            uint32_t abase = sb + FQ_ + (uint32_t)(c * 8192 + (fm * 32 + lr) * 64);
            uint32_t bbase = sb + FKV_ + (uint32_t)(((c & 1) * 16384)
                           + (fn * 32 + lr) * 64);
            #pragma unroll
            for (int s = 0; s < 2; s++) {
                uint32_t co = (uint32_t)(((s << 1) | cx) ^ swz) << 4;
                uint32_t A1[2][4], A2[2][4], Bf[4][2];
                #pragma unroll
                for (int mi = 0; mi < 2; mi++)
                    ldsm4(A1[mi][0], A1[mi][1], A1[mi][2], A1[mi][3],
                          abase + (uint32_t)(mi * 1024) + co);
                #pragma unroll
                for (int np = 0; np < 2; np++) {
                    uint32_t r0, r1, r2, r3;
                    ldsm4(r0, r1, r2, r3, bbase + (uint32_t)(np * 1024) + co);
                    Bf[2 * np][0] = r0; Bf[2 * np][1] = r2;
                    Bf[2 * np + 1][0] = r1; Bf[2 * np + 1][1] = r3;
                }
                #pragma unroll
                for (int mi = 0; mi < 2; mi++)
                    #pragma unroll
                    for (int ni = 0; ni < 4; ni++)
                        mma16816(sacc[mi][ni], A1[mi], Bf[ni]);
                #pragma unroll
                for (int mi = 0; mi < 2; mi++)
                    ldsm4(A2[mi][0], A2[mi][1], A2[mi][2], A2[mi][3],
                          abase + (uint32_t)(mi * 1024) + co + 4096);
                #pragma unroll
                for (int mi = 0; mi < 2; mi++)
                    #pragma unroll
                    for (int ni = 0; ni < 4; ni++)
                        mma16816(sacc[mi][ni], A2[mi], Bf[ni]);
                #pragma unroll
                for (int np = 0; np < 2; np++) {
                    uint32_t r0, r1, r2, r3;
                    ldsm4(r0, r1, r2, r3, bbase + (uint32_t)(np * 1024) + co + 8192);
                    Bf[2 * np][0] = r0; Bf[2 * np][1] = r2;
                    Bf[2 * np + 1][0] = r1; Bf[2 * np + 1][1] = r3;
                }
                #pragma unroll
                for (int mi = 0; mi < 2; mi++)
                    #pragma unroll
                    for (int ni = 0; ni < 4; ni++)
                        mma16816(sacc[mi][ni], A1[mi], Bf[ni]);
            }
        }

        float rmax[2][2];
        #pragma unroll
        for (int mi = 0; mi < 2; mi++)
            #pragma unroll
            for (int h2 = 0; h2 < 2; h2++) {
                float m = -1e30f;
                #pragma unroll
                for (int ni = 0; ni < 4; ni++)
                    m = fmaxf(m, fmaxf(sacc[mi][ni][h2 * 2], sacc[mi][ni][h2 * 2 + 1]));
                #pragma unroll
                for (int o = 1; o <= 2; o <<= 1)
                    m = fmaxf(m, __shfl_xor_sync(0xffffffffu, m, o));
                rmax[mi][h2] = m;
            }
        if ((lane & 3) == 0)
            #pragma unroll
            for (int mi = 0; mi < 2; mi++)
                #pragma unroll
                for (int h2 = 0; h2 < 2; h2++)
                    RM[(rbase + mi * 16 + h2 * 8) * 4 + fn] = rmax[mi][h2];
        __syncthreads();

        load_v(0, 0, j);

        float mnew[2][2], fact[2][2], rsum[2][2];
        #pragma unroll
        for (int mi = 0; mi < 2; mi++)
            #pragma unroll
            for (int h2 = 0; h2 < 2; h2++) {
                int r = rbase + mi * 16 + h2 * 8;
                float bm = fmaxf(fmaxf(RM[r * 4 + 0], RM[r * 4 + 1]),
                                 fmaxf(RM[r * 4 + 2], RM[r * 4 + 3]));
                float mo = Mv[r];
                float mn = fmaxf(mo, bm);
                mnew[mi][h2] = mn;
                fact[mi][h2] = __expf(mo - mn);
                rsum[mi][h2] = 0.f;
            }
        #pragma unroll
        for (int mi = 0; mi < 2; mi++)
            #pragma unroll
            for (int ni = 0; ni < 4; ni++)
                #pragma unroll
                for (int e = 0; e < 4; e++) {
                    int h2 = e >> 1;
                    oacc[mi][ni][e] *= fact[mi][h2];
                    float p = __expf(sacc[mi][ni][e] - mnew[mi][h2]);
                    sacc[mi][ni][e] = p;
                    rsum[mi][h2] += p;
                }
        #pragma unroll
        for (int o = 1; o <= 2; o <<= 1)
            #pragma unroll
            for (int mi = 0; mi < 2; mi++)
                #pragma unroll
                for (int h2 = 0; h2 < 2; h2++)
                    rsum[mi][h2] += __shfl_xor_sync(0xffffffffu, rsum[mi][h2], o);
        if ((lane & 3) == 0)
            #pragma unroll
            for (int mi = 0; mi < 2; mi++)
                #pragma unroll
                for (int h2 = 0; h2 < 2; h2++)
                    RS[(rbase + mi * 16 + h2 * 8) * 4 + fn] = rsum[mi][h2];
        #pragma unroll
        for (int mi = 0; mi < 2; mi++)
            #pragma unroll
            for (int h2 = 0; h2 < 2; h2++) {
                int rl = rbase + mi * 16 + h2 * 8;
                int key = (rl >> 1) & 3;
                uint32_t rowb = sb + FP_ + (uint32_t)(fn * 4096) + (uint32_t)(rl * 64);
                #pragma unroll
                for (int ni = 0; ni < 4; ni++) {
                    int cc = cq + ni * 8;
                    uint32_t boff = rowb
                        + (uint32_t)((((cc >> 3) ^ key) << 4) + (cc & 7) * 2);
                    float p0 = sacc[mi][ni][h2 * 2];
                    float p1 = sacc[mi][ni][h2 * 2 + 1];
                    st32(boff,         pack_hi2(p0, p1));
                    st32(boff + 16384, pack_lo2(p0, p1));
                }
            }
        __syncthreads();
        if (fn == 0 && (lane & 3) == 0)
            #pragma unroll
            for (int mi = 0; mi < 2; mi++)
                #pragma unroll
                for (int h2 = 0; h2 < 2; h2++) {
                    int r = rbase + mi * 16 + h2 * 8;
                    Mv[r] = mnew[mi][h2];
                    Lv[r] = Lv[r] * fact[mi][h2]
                          + RS[r * 4] + RS[r * 4 + 1] + RS[r * 4 + 2] + RS[r * 4 + 3];
                }

        for (int c = 0; c < 4; c++) {
            cp_wait<0>();
            __syncthreads();
            if (c < 3) load_v((c + 1) & 1, c + 1, j);
            uint32_t pbase = sb + FP_ + (uint32_t)(c * 4096)
                           + (uint32_t)((fm * 32 + lr) * 64);
            uint32_t vbase = sb + FKV_ + (uint32_t)(((c & 1) * 16384)
                           + (fn * 32 + lr) * 64);
            #pragma unroll
            for (int s = 0; s < 2; s++) {
                uint32_t co = (uint32_t)(((s << 1) | cx) ^ swz) << 4;
                uint32_t A1[2][4], A2[2][4], Bf[4][2];
                #pragma unroll
                for (int mi = 0; mi < 2; mi++)
                    ldsm4(A1[mi][0], A1[mi][1], A1[mi][2], A1[mi][3],
                          pbase + (uint32_t)(mi * 1024) + co);
                #pragma unroll
                for (int np = 0; np < 2; np++) {
                    uint32_t r0, r1, r2, r3;
                    ldsm4(r0, r1, r2, r3, vbase + (uint32_t)(np * 1024) + co);
                    Bf[2 * np][0] = r0; Bf[2 * np][1] = r2;
                    Bf[2 * np + 1][0] = r1; Bf[2 * np + 1][1] = r3;
                }
                #pragma unroll
                for (int mi = 0; mi < 2; mi++)
                    #pragma unroll
                    for (int ni = 0; ni < 4; ni++)
                        mma16816(oacc[mi][ni], A1[mi], Bf[ni]);
                #pragma unroll
                for (int mi = 0; mi < 2; mi++)
                    ldsm4(A2[mi][0], A2[mi][1], A2[mi][2], A2[mi][3],
                          pbase + (uint32_t)(mi * 1024) + co + 16384);
                #pragma unroll
                for (int mi = 0; mi < 2; mi++)
                    #pragma unroll
                    for (int ni = 0; ni < 4; ni++)
                        mma16816(oacc[mi][ni], A2[mi], Bf[ni]);
                #pragma unroll
                for (int np = 0; np < 2; np++) {
                    uint32_t r0, r1, r2, r3;
                    ldsm4(r0, r1, r2, r3, vbase + (uint32_t)(np * 1024) + co + 8192);
                    Bf[2 * np][0] = r0; Bf[2 * np][1] = r2;
                    Bf[2 * np + 1][0] = r1; Bf[2 * np + 1][1] = r3;
                }
                #pragma unroll
                for (int mi = 0; mi < 2; mi++)
                    #pragma unroll
                    for (int ni = 0; ni < 4; ni++)
                        mma16816(oacc[mi][ni], A1[mi], Bf[ni]);
            }
        }
        __syncthreads();
    }

    #pragma unroll
    for (int mi = 0; mi < 2; mi++)
        #pragma unroll
        for (int h2 = 0; h2 < 2; h2++) {
            int rl = rbase + mi * 16 + h2 * 8;
            float li = 1.f / Lv[rl];
            long long row = (qrow0 + rl) * (long long)DIM_ + hcol + fn * 32;
            #pragma unroll
            for (int ni = 0; ni < 4; ni++) {
                float v0 = oacc[mi][ni][h2 * 2] * li;
                float v1 = oacc[mi][ni][h2 * 2 + 1] * li;
                long long o = row + cq + ni * 8;
                *(uint32_t*)(oh + o) = pack_hi2(v0, v1);
                *(uint32_t*)(ol + o) = pack_lo2(v0, v1);
            }
        }
}

// ---------------------------------------------------------------------------
extern "C" void kernel_launch(void* const* d_in, const int* in_sizes, int n_in,
                              void* d_out, int out_size) {
    const float* x      = (const float*)d_in[0];
    const float* emb    = (const float*)d_in[1];
    const float* W_emb  = (const float*)d_in[2];
    const float* b_emb  = (const float*)d_in[3];
    const float* g_norm = (const float*)d_in[4];
    const float* W_qkv  = (const float*)d_in[5];
    const float* g_q    = (const float*)d_in[6];
    const float* g_k    = (const float*)d_in[7];
    const float* W_out  = (const float*)d_in[8];
    float* out = (float*)d_out;
    (void)in_sizes; (void)n_in; (void)out_size;

    float *ss, *ssp;
    __nv_bfloat16 *xnh, *xnl, *wqTh, *wqTl, *woTh, *woTl;
    __nv_bfloat16 *qkh, *qkl, *vTh, *vTl, *oh, *ol;
    cudaGetSymbolAddress((void**)&ss,   g_ss);
    cudaGetSymbolAddress((void**)&ssp,  g_ssp);
    cudaGetSymbolAddress((void**)&xnh,  g_xnh);
    cudaGetSymbolAddress((void**)&xnl,  g_xnl);
    cudaGetSymbolAddress((void**)&wqTh, g_wqTh);
    cudaGetSymbolAddress((void**)&wqTl, g_wqTl);
    cudaGetSymbolAddress((void**)&woTh, g_woTh);
    cudaGetSymbolAddress((void**)&woTl, g_woTl);
    cudaGetSymbolAddress((void**)&qkh,  g_qkh);
    cudaGetSymbolAddress((void**)&qkl,  g_qkl);
    cudaGetSymbolAddress((void**)&vTh,  g_vTh);
    cudaGetSymbolAddress((void**)&vTl,  g_vTl);
    cudaGetSymbolAddress((void**)&oh,   g_oh);
    cudaGetSymbolAddress((void**)&ol,   g_ol);

    cudaFuncSetAttribute(gemm_bf16x3,
                         cudaFuncAttributeMaxDynamicSharedMemorySize, GEMM_SMEM);
    cudaFuncSetAttribute(flash_attn,
                         cudaFuncAttributeMaxDynamicSharedMemorySize, FLASH_SMEM);

    static cudaStream_t s2 = nullptr;
    static cudaEvent_t evFork = nullptr, evJoin = nullptr;
    if (s2 == nullptr) {
        cudaStreamCreateWithFlags(&s2, cudaStreamNonBlocking);
        cudaEventCreateWithFlags(&evFork, cudaEventDisableTiming);
        cudaEventCreateWithFlags(&evJoin, cudaEventDisableTiming);
    }

    cudaEventRecord(evFork, 0);
    cudaStreamWaitEvent(s2, evFork, 0);
    k_tsplit<<<dim3(QKVC_ / 32, DIM_ / 32), dim3(32, 8), 0, s2>>>(
        W_qkv, DIM_, QKVC_, wqTh, wqTl);
    k_tsplit<<<dim3(DIM_ / 32, DIM_ / 32), dim3(32, 8), 0, s2>>>(
        W_out, DIM_, DIM_, woTh, woTl);
    cudaEventRecord(evJoin, s2);

    k_ss_part<<<dim3((2 * DIM_) / 256, B_, SK_), 256>>>(emb, W_emb, ssp);
    k_ss_reduce<<<dim3((2 * DIM_) / 256, B_), 256>>>(ssp, b_emb, ss);
    k_xnorm<<<TOK_, 256>>>(x, g_norm, ss, xnh, xnl);

    cudaStreamWaitEvent(0, evJoin, 0);

    gemm_bf16x3<<<dim3(QKVC_ / 128, TOK_ / 128, 1), 256, GEMM_SMEM>>>(
        xnh, xnl, DIM_, wqTh, wqTl, DIM_, nullptr, nullptr, nullptr, 0, DIM_,
        g_q, g_k, qkh, qkl, vTh, vTl);
    flash_attn<<<dim3(N_ / 64, BH_), 256, FLASH_SMEM>>>(
        qkh, qkl, vTh, vTl, oh, ol);
    gemm_bf16x3<<<dim3(DIM_ / 128, TOK_ / 128, 1), 256, GEMM_SMEM>>>(
        oh, ol, DIM_, woTh, woTl, DIM_, oh, ol, out, DIM_, DIM_,
        nullptr, nullptr, nullptr, nullptr, nullptr, nullptr);
}